// round 6
// baseline (speedup 1.0000x reference)
#include <cuda_runtime.h>
#include <cuda_bf16.h>
#include <cuda_fp16.h>
#include <cstdint>

#define Bn 8
#define Nn 1024
#define En 256
#define Hn 8
#define Dn 32
#define Cn 4

#define QSZ (Bn * Hn * Nn * Dn)            // 2M elems
__device__ float d_V[QSZ];
__device__ __nv_bfloat16 g_xhi[Bn * Nn * En], g_xlo[Bn * Nn * En];
__device__ __nv_bfloat16 g_qhi[QSZ], g_qlo[QSZ];
__device__ __nv_bfloat16 g_khi[QSZ], g_klo[QSZ];
__device__ __nv_bfloat16 g_vthi[QSZ], g_vtlo[QSZ];   // [B,H,D,N]
__device__ __nv_bfloat16 g_chi[Bn * Nn * En], g_clo[Bn * Nn * En];
__device__ __nv_bfloat16 g_wthi[4 * En * En], g_wtlo[4 * En * En];  // W^T splits

#define SCALEQ 0.25506807163967554f   // 1/sqrt(32) * log2e
#define LOG2E  1.4426950408889634f

__device__ __forceinline__ float ex2(float x) {
    float y;
    asm("ex2.approx.f32 %0, %1;" : "=f"(y) : "f"(x));
    return y;
}
__device__ __forceinline__ uint32_t bits2(__nv_bfloat162 v) {
    return *reinterpret_cast<uint32_t*>(&v);
}
__device__ __forceinline__ uint32_t bitsh2(__half2 v) {
    return *reinterpret_cast<uint32_t*>(&v);
}
__device__ __forceinline__ uint2 pack4bf(float a, float b, float c, float d) {
    uint2 r;
    r.x = bits2(__floats2bfloat162_rn(a, b));
    r.y = bits2(__floats2bfloat162_rn(c, d));
    return r;
}
__device__ __forceinline__ void split2(float a, float b, uint32_t& h, uint32_t& l) {
    __nv_bfloat162 hp = __floats2bfloat162_rn(a, b);
    h = bits2(hp);
    l = bits2(__floats2bfloat162_rn(a - __low2float(hp), b - __high2float(hp)));
}

#define MMA(c, a, b0, b1)                                                     \
    asm volatile("mma.sync.aligned.m16n8k16.row.col.f32.bf16.bf16.f32 "       \
        "{%0,%1,%2,%3}, {%4,%5,%6,%7}, {%8,%9}, {%0,%1,%2,%3};"               \
        : "+f"((c)[0]), "+f"((c)[1]), "+f"((c)[2]), "+f"((c)[3])              \
        : "r"((a)[0]), "r"((a)[1]), "r"((a)[2]), "r"((a)[3]), "r"(b0), "r"(b1))

// ============================================================================
// convert x -> bf16 hi/lo
// ============================================================================
__global__ __launch_bounds__(256)
void convert_x(const float* __restrict__ x)
{
    int i = blockIdx.x * 256 + threadIdx.x;   // per float4
    float4 v = ((const float4*)x)[i];
    float f[4] = {v.x, v.y, v.z, v.w};
    float hi[4], lo[4];
#pragma unroll
    for (int t = 0; t < 4; t++) {
        hi[t] = __bfloat162float(__float2bfloat16_rn(f[t]));
        lo[t] = f[t] - hi[t];
    }
    ((uint2*)g_xhi)[i] = pack4bf(hi[0], hi[1], hi[2], hi[3]);
    ((uint2*)g_xlo)[i] = pack4bf(lo[0], lo[1], lo[2], lo[3]);
}

// ============================================================================
// convert W -> W^T bf16 hi/lo (32x32 tiles)
// ============================================================================
__global__ __launch_bounds__(256)
void convert_wt(const float* __restrict__ W0, const float* __restrict__ W1,
                const float* __restrict__ W2, const float* __restrict__ W3)
{
    __shared__ float T[32][33];
    const int z = blockIdx.x >> 6;
    const int tile = blockIdx.x & 63;
    const int k0 = (tile >> 3) * 32;
    const int n0 = (tile & 7) * 32;
    const float* W = (z == 0) ? W0 : (z == 1) ? W1 : (z == 2) ? W2 : W3;
    const int tid = threadIdx.x;
    {
        int r = tid >> 3, c4 = tid & 7;
        float4 v = *(const float4*)&W[(k0 + r) * En + n0 + c4 * 4];
        T[r][c4 * 4 + 0] = v.x; T[r][c4 * 4 + 1] = v.y;
        T[r][c4 * 4 + 2] = v.z; T[r][c4 * 4 + 3] = v.w;
    }
    __syncthreads();
    {
        int r = tid >> 3, c4 = tid & 7;
        float f[4], hi[4], lo[4];
#pragma unroll
        for (int u = 0; u < 4; u++) {
            f[u] = T[c4 * 4 + u][r];
            hi[u] = __bfloat162float(__float2bfloat16_rn(f[u]));
            lo[u] = f[u] - hi[u];
        }
        int off = z * En * En + (n0 + r) * En + k0 + c4 * 4;
        *(uint2*)&g_wthi[off] = pack4bf(hi[0], hi[1], hi[2], hi[3]);
        *(uint2*)&g_wtlo[off] = pack4bf(lo[0], lo[1], lo[2], lo[3]);
    }
}

// ============================================================================
// tensor-core split-bf16 GEMM: C[128x64] tile of A[8192x256] @ B^T.
// MODE 0: QKV (z=blockIdx.z; epilogue -> split Q(scaled)/K, fp32 V)
// MODE 1: out-proj (A=g_chi/clo, W slot 3; epilogue -> +bo +x -> out)
// ============================================================================
#define GA_HI 0
#define GA_LO 2560
#define GB_HI 5120
#define GB_LO 6400
#define GSM_W 7680

template <int MODE>
__global__ __launch_bounds__(256)
void gemm_tc(const float* __restrict__ bias0, const float* __restrict__ bias1,
             const float* __restrict__ bias2,
             const float* __restrict__ X, float* __restrict__ OutR)
{
    __shared__ __align__(16) uint32_t S[GSM_W];
    const int tid = threadIdx.x;
    const int w = tid >> 5, lane = tid & 31;
    const int g = lane >> 2, t = lane & 3;
    const int row0 = blockIdx.y * 128;
    const int col0 = blockIdx.x * 64;
    const int z = (MODE == 0) ? blockIdx.z : 3;

    const uint4* ah4 = (const uint4*)((MODE == 0) ? g_xhi : g_chi);
    const uint4* al4 = (const uint4*)((MODE == 0) ? g_xlo : g_clo);
    const uint4* bh4 = (const uint4*)(g_wthi + z * En * En);
    const uint4* bl4 = (const uint4*)(g_wtlo + z * En * En);

    float c_[8][4] = {};

    const int a_row = tid >> 1;
    const int a_c4 = (tid & 1) * 2;
    const int b_row = tid >> 2;
    const int b_c4 = tid & 3;

    for (int kc = 0; kc < 8; kc++) {
        {
            size_t si = (size_t)(row0 + a_row) * 32 + kc * 4 + a_c4;
            *(uint4*)&S[GA_HI + a_row * 20 + a_c4 * 4] = ah4[si];
            *(uint4*)&S[GA_HI + a_row * 20 + (a_c4 + 1) * 4] = ah4[si + 1];
            *(uint4*)&S[GA_LO + a_row * 20 + a_c4 * 4] = al4[si];
            *(uint4*)&S[GA_LO + a_row * 20 + (a_c4 + 1) * 4] = al4[si + 1];
        }
        {
            size_t si = (size_t)(col0 + b_row) * 32 + kc * 4 + b_c4;
            *(uint4*)&S[GB_HI + b_row * 20 + b_c4 * 4] = bh4[si];
            *(uint4*)&S[GB_LO + b_row * 20 + b_c4 * 4] = bl4[si];
        }
        __syncthreads();
#pragma unroll
        for (int kt = 0; kt < 2; kt++) {
            const int aw = (w * 16 + g) * 20 + kt * 8 + t;
            uint32_t ah[4], al[4];
            ah[0] = S[GA_HI + aw];       ah[1] = S[GA_HI + aw + 160];
            ah[2] = S[GA_HI + aw + 4];   ah[3] = S[GA_HI + aw + 164];
            al[0] = S[GA_LO + aw];       al[1] = S[GA_LO + aw + 160];
            al[2] = S[GA_LO + aw + 4];   al[3] = S[GA_LO + aw + 164];
#pragma unroll
            for (int nt = 0; nt < 8; nt++) {
                const int kw = (nt * 8 + g) * 20 + kt * 8 + t;
                uint32_t b0h = S[GB_HI + kw], b1h = S[GB_HI + kw + 4];
                uint32_t b0l = S[GB_LO + kw], b1l = S[GB_LO + kw + 4];
                MMA(c_[nt], ah, b0h, b1h);
                MMA(c_[nt], al, b0h, b1h);
                MMA(c_[nt], ah, b0l, b1l);
            }
        }
        __syncthreads();
    }

    const int m = row0 + w * 16 + g;
    if (MODE == 0) {
        const float* bias = (z == 0) ? bias0 : (z == 1) ? bias1 : bias2;
        const int b = m >> 10, n = m & 1023;
#pragma unroll
        for (int nt = 0; nt < 8; nt++) {
            int col = col0 + nt * 8 + 2 * t;
            float bz0 = bias[col], bz1 = bias[col + 1];
            float v0 = c_[nt][0] + bz0, v1 = c_[nt][1] + bz1;
            float v2 = c_[nt][2] + bz0, v3 = c_[nt][3] + bz1;
            int h = col >> 5, dd = col & 31;
            size_t oA = ((size_t)(b * Hn + h) * Nn + n) * Dn + dd;
            size_t oB = oA + 8 * Dn;
            if (z == 0) {
                v0 *= SCALEQ; v1 *= SCALEQ; v2 *= SCALEQ; v3 *= SCALEQ;
                uint32_t hA, lA, hB, lB;
                split2(v0, v1, hA, lA);
                split2(v2, v3, hB, lB);
                *(uint32_t*)&g_qhi[oA] = hA; *(uint32_t*)&g_qlo[oA] = lA;
                *(uint32_t*)&g_qhi[oB] = hB; *(uint32_t*)&g_qlo[oB] = lB;
            } else if (z == 1) {
                uint32_t hA, lA, hB, lB;
                split2(v0, v1, hA, lA);
                split2(v2, v3, hB, lB);
                *(uint32_t*)&g_khi[oA] = hA; *(uint32_t*)&g_klo[oA] = lA;
                *(uint32_t*)&g_khi[oB] = hB; *(uint32_t*)&g_klo[oB] = lB;
            } else {
                float2 p0 = {v0, v1}, p1 = {v2, v3};
                *(float2*)&d_V[oA] = p0;
                *(float2*)&d_V[oB] = p1;
            }
        }
    } else {
#pragma unroll
        for (int nt = 0; nt < 8; nt++) {
            int col = col0 + nt * 8 + 2 * t;
            float bz0 = bias0[col], bz1 = bias0[col + 1];
            float2 xA = *(const float2*)&X[(size_t)m * En + col];
            float2 xB = *(const float2*)&X[(size_t)(m + 8) * En + col];
            float2 oA = {c_[nt][0] + bz0 + xA.x, c_[nt][1] + bz1 + xA.y};
            float2 oB = {c_[nt][2] + bz0 + xB.x, c_[nt][3] + bz1 + xB.y};
            *(float2*)&OutR[(size_t)m * En + col] = oA;
            *(float2*)&OutR[(size_t)(m + 8) * En + col] = oB;
        }
    }
}

// ============================================================================
// transpose V to [B,H,D,N] + split
// ============================================================================
__global__ __launch_bounds__(256)
void transpose_v()
{
    __shared__ float T[32][36];
    const int tid = threadIdx.x;
    const int blk = blockIdx.x;
    const int bh = blk >> 5, jt = blk & 31;
    const int j0 = jt * 32;
    {
        int r = tid >> 3, c = tid & 7;
        float4 v = *(const float4*)&d_V[(bh * Nn + j0 + r) * Dn + c * 4];
        *(float4*)&T[r][c * 4] = v;
    }
    __syncthreads();
    {
        int d = tid >> 3, c = tid & 7;
        float f[4], hi[4], lo[4];
#pragma unroll
        for (int u = 0; u < 4; u++) {
            f[u] = T[c * 4 + u][d];
            hi[u] = __bfloat162float(__float2bfloat16_rn(f[u]));
            lo[u] = f[u] - hi[u];
        }
        int off = (bh * Dn + d) * Nn + j0 + c * 4;
        *(uint2*)&g_vthi[off] = pack4bf(hi[0], hi[1], hi[2], hi[3]);
        *(uint2*)&g_vtlo[off] = pack4bf(lo[0], lo[1], lo[2], lo[3]);
    }
}

// ============================================================================
// tensor-core flash attention, adjacency bias FUSED (adj read in-kernel).
// grid: (h, i-tile, b) — h fastest so co-resident head-blocks share adj via L2.
// ============================================================================
#define KHI_W 0
#define KLO_W 1280
#define VTHI_W 2560
#define VTLO_W 3712
#define BIAS_W 4864
#define SMEM_W 9472

__global__ __launch_bounds__(256)
void attn_tc(const float* __restrict__ adj, const float* __restrict__ Wa)
{
    __shared__ __align__(16) uint32_t S[SMEM_W];
    const int tid = threadIdx.x;
    const int w = tid >> 5, lane = tid & 31;
    const int g = lane >> 2, t = lane & 3;
    const int h = blockIdx.x;
    const int i0 = blockIdx.y * 128;
    const int b = blockIdx.z;
    const int bh = b * Hn + h;

    // Wa column for this head, log2e-scaled (ba is constant per row -> cancels in softmax)
    const float wa0 = Wa[0 * Hn + h] * LOG2E;
    const float wa1 = Wa[1 * Hn + h] * LOG2E;
    const float wa2 = Wa[2 * Hn + h] * LOG2E;
    const float wa3 = Wa[3 * Hn + h] * LOG2E;

    const uint32_t* q32h = (const uint32_t*)g_qhi;
    const uint32_t* q32l = (const uint32_t*)g_qlo;
    const int rowA = bh * Nn + i0 + w * 16 + g;
    const int rowB = rowA + 8;
    uint32_t aQh[2][4], aQl[2][4];
#pragma unroll
    for (int kt = 0; kt < 2; kt++) {
        aQh[kt][0] = q32h[rowA * 16 + kt * 8 + t];
        aQh[kt][1] = q32h[rowB * 16 + kt * 8 + t];
        aQh[kt][2] = q32h[rowA * 16 + kt * 8 + 4 + t];
        aQh[kt][3] = q32h[rowB * 16 + kt * 8 + 4 + t];
        aQl[kt][0] = q32l[rowA * 16 + kt * 8 + t];
        aQl[kt][1] = q32l[rowB * 16 + kt * 8 + t];
        aQl[kt][2] = q32l[rowA * 16 + kt * 8 + 4 + t];
        aQl[kt][3] = q32l[rowB * 16 + kt * 8 + 4 + t];
    }

    float O[4][4] = {};
    float mA = -1e30f, mB = -1e30f, lA = 0.f, lB = 0.f;

    const uint4* kh4 = (const uint4*)g_khi;
    const uint4* kl4 = (const uint4*)g_klo;
    const uint4* vh4 = (const uint4*)g_vthi;
    const uint4* vl4 = (const uint4*)g_vtlo;
    // adj base for this (b, i0): element (il, j) is float4 at index il*Nn + j
    const float4* adjp = (const float4*)&adj[((size_t)(b * Nn + i0)) * Nn * Cn];

    for (int jt = 0; jt < 16; jt++) {
        const int j0 = jt * 64;
        {
            int row = tid >> 2, c = tid & 3;
            uint4 v1 = kh4[(bh * Nn + j0 + row) * 4 + c];
            uint4 v2 = kl4[(bh * Nn + j0 + row) * 4 + c];
            *(uint4*)&S[KHI_W + row * 20 + c * 4] = v1;
            *(uint4*)&S[KLO_W + row * 20 + c * 4] = v2;
        }
        {
            int d = tid >> 3, c = tid & 7;
            uint4 v1 = vh4[(bh * Dn + d) * 128 + jt * 8 + c];
            uint4 v2 = vl4[(bh * Dn + d) * 128 + jt * 8 + c];
            *(uint4*)&S[VTHI_W + d * 36 + c * 4] = v1;
            *(uint4*)&S[VTLO_W + d * 36 + c * 4] = v2;
        }
        // ---- fused bias: load adj, dot with Wa (log2e-scaled), store half2 ----
#pragma unroll
        for (int u = 0; u < 16; u++) {
            int p = u * 256 + tid;           // pair index: 128 rows x 32 pairs
            int il = p >> 5, jp = p & 31;
            size_t e = (size_t)il * Nn + j0 + 2 * jp;
            float4 a0 = adjp[e];
            float4 a1 = adjp[e + 1];
            float v0 = a0.x * wa0 + a0.y * wa1 + a0.z * wa2 + a0.w * wa3;
            float v1 = a1.x * wa0 + a1.y * wa1 + a1.z * wa2 + a1.w * wa3;
            S[BIAS_W + il * 36 + jp] = bitsh2(__floats2half2_rn(v0, v1));
        }
        __syncthreads();

        float c_[8][4] = {};
#pragma unroll
        for (int nt = 0; nt < 8; nt++) {
#pragma unroll
            for (int kt = 0; kt < 2; kt++) {
                int kw = (nt * 8 + g) * 20 + kt * 8 + t;
                uint32_t bh0 = S[KHI_W + kw], bh1 = S[KHI_W + kw + 4];
                uint32_t bl0 = S[KLO_W + kw], bl1 = S[KLO_W + kw + 4];
                MMA(c_[nt], aQh[kt], bh0, bh1);
                MMA(c_[nt], aQl[kt], bh0, bh1);
                MMA(c_[nt], aQh[kt], bl0, bl1);
            }
        }
        const int biA = (w * 16 + g) * 36;
        const int biB = (w * 16 + g + 8) * 36;
#pragma unroll
        for (int nt = 0; nt < 8; nt++) {
            uint32_t u0 = S[BIAS_W + biA + nt * 4 + t];
            uint32_t u1 = S[BIAS_W + biB + nt * 4 + t];
            __half2 h0 = *(__half2*)&u0;
            __half2 h1 = *(__half2*)&u1;
            c_[nt][0] += __low2float(h0);
            c_[nt][1] += __high2float(h0);
            c_[nt][2] += __low2float(h1);
            c_[nt][3] += __high2float(h1);
        }
        float tA = -1e30f, tB = -1e30f;
#pragma unroll
        for (int nt = 0; nt < 8; nt++) {
            tA = fmaxf(tA, fmaxf(c_[nt][0], c_[nt][1]));
            tB = fmaxf(tB, fmaxf(c_[nt][2], c_[nt][3]));
        }
        tA = fmaxf(tA, __shfl_xor_sync(0xffffffffu, tA, 1));
        tA = fmaxf(tA, __shfl_xor_sync(0xffffffffu, tA, 2));
        tB = fmaxf(tB, __shfl_xor_sync(0xffffffffu, tB, 1));
        tB = fmaxf(tB, __shfl_xor_sync(0xffffffffu, tB, 2));
        float mnA = fmaxf(mA, tA), mnB = fmaxf(mB, tB);
        float cA = ex2(mA - mnA), cB = ex2(mB - mnB);
        mA = mnA; mB = mnB;
        lA *= cA; lB *= cB;
#pragma unroll
        for (int dnt = 0; dnt < 4; dnt++) {
            O[dnt][0] *= cA; O[dnt][1] *= cA;
            O[dnt][2] *= cB; O[dnt][3] *= cB;
        }
        uint32_t PH[8], PH2[8], PL[8], PL2[8];
#pragma unroll
        for (int nt = 0; nt < 8; nt++) {
            float p0 = ex2(c_[nt][0] - mA), p1 = ex2(c_[nt][1] - mA);
            float p2 = ex2(c_[nt][2] - mB), p3 = ex2(c_[nt][3] - mB);
            lA += p0 + p1;
            lB += p2 + p3;
            __nv_bfloat162 x01 = __floats2bfloat162_rn(p0, p1);
            __nv_bfloat162 x23 = __floats2bfloat162_rn(p2, p3);
            PH[nt]  = bits2(x01);
            PH2[nt] = bits2(x23);
            PL[nt]  = bits2(__floats2bfloat162_rn(p0 - __low2float(x01), p1 - __high2float(x01)));
            PL2[nt] = bits2(__floats2bfloat162_rn(p2 - __low2float(x23), p3 - __high2float(x23)));
        }
#pragma unroll
        for (int dnt = 0; dnt < 4; dnt++) {
#pragma unroll
            for (int u = 0; u < 4; u++) {
                int vw = (dnt * 8 + g) * 36 + u * 8 + t;
                uint32_t vh0 = S[VTHI_W + vw], vh1 = S[VTHI_W + vw + 4];
                uint32_t vl0 = S[VTLO_W + vw], vl1 = S[VTLO_W + vw + 4];
                uint32_t aP[4]  = {PH[2 * u], PH2[2 * u], PH[2 * u + 1], PH2[2 * u + 1]};
                uint32_t aPl[4] = {PL[2 * u], PL2[2 * u], PL[2 * u + 1], PL2[2 * u + 1]};
                MMA(O[dnt], aP, vh0, vh1);
                MMA(O[dnt], aPl, vh0, vh1);
                MMA(O[dnt], aP, vl0, vl1);
            }
        }
        __syncthreads();
    }

    lA += __shfl_xor_sync(0xffffffffu, lA, 1);
    lA += __shfl_xor_sync(0xffffffffu, lA, 2);
    lB += __shfl_xor_sync(0xffffffffu, lB, 1);
    lB += __shfl_xor_sync(0xffffffffu, lB, 2);
    const float iA = 1.f / lA, iB = 1.f / lB;

    const int nA = rowA & (Nn - 1);
    const size_t baseA = ((size_t)b * Nn + nA) * En + h * Dn;
    const size_t baseB = baseA + 8 * En;
#pragma unroll
    for (int dnt = 0; dnt < 4; dnt++) {
        int dd = dnt * 8 + 2 * t;
        uint32_t hA, lA2, hB, lB2;
        split2(O[dnt][0] * iA, O[dnt][1] * iA, hA, lA2);
        split2(O[dnt][2] * iB, O[dnt][3] * iB, hB, lB2);
        *(uint32_t*)&g_chi[baseA + dd] = hA;
        *(uint32_t*)&g_clo[baseA + dd] = lA2;
        *(uint32_t*)&g_chi[baseB + dd] = hB;
        *(uint32_t*)&g_clo[baseB + dd] = lB2;
    }
}

// ============================================================================
extern "C" void kernel_launch(void* const* d_in, const int* in_sizes, int n_in,
                              void* d_out, int out_size)
{
    const float* x   = (const float*)d_in[0];
    const float* adj = (const float*)d_in[1];
    const float* Wq  = (const float*)d_in[2];
    const float* bq  = (const float*)d_in[3];
    const float* Wk  = (const float*)d_in[4];
    const float* bk  = (const float*)d_in[5];
    const float* Wv  = (const float*)d_in[6];
    const float* bv  = (const float*)d_in[7];
    const float* Wo  = (const float*)d_in[8];
    const float* bo  = (const float*)d_in[9];
    const float* Wa  = (const float*)d_in[10];
    float* out = (float*)d_out;

    convert_x<<<(Bn * Nn * En / 4) / 256, 256>>>(x);
    convert_wt<<<4 * 64, 256>>>(Wq, Wk, Wv, Wo);

    dim3 gq(En / 64, (Bn * Nn) / 128, 3);
    gemm_tc<0><<<gq, 256>>>(bq, bk, bv, nullptr, nullptr);

    transpose_v<<<Bn * Hn * (Nn / 32), 256>>>();

    dim3 ga(Hn, Nn / 128, Bn);     // h fastest -> co-resident heads share adj via L2
    attn_tc<<<ga, 256>>>(adj, Wa);

    dim3 go(En / 64, (Bn * Nn) / 128);
    gemm_tc<1><<<go, 256>>>(bo, bo, bo, x, out);
}

// round 7
// speedup vs baseline: 1.4428x; 1.4428x over previous
#include <cuda_runtime.h>
#include <cuda_bf16.h>
#include <cuda_fp16.h>
#include <cstdint>

#define Bn 8
#define Nn 1024
#define En 256
#define Hn 8
#define Dn 32
#define Cn 4

#define QSZ (Bn * Hn * Nn * Dn)            // 2M elems
__device__ float d_V[QSZ];
__device__ __nv_bfloat16 g_xhi[Bn * Nn * En], g_xlo[Bn * Nn * En];
__device__ __nv_bfloat16 g_qhi[QSZ], g_qlo[QSZ];
__device__ __nv_bfloat16 g_khi[QSZ], g_klo[QSZ];
__device__ __nv_bfloat16 g_vthi[QSZ], g_vtlo[QSZ];   // [B,H,D,N]
__device__ __nv_bfloat16 g_chi[Bn * Nn * En], g_clo[Bn * Nn * En];
__device__ __nv_bfloat16 g_wthi[4 * En * En], g_wtlo[4 * En * En];  // W^T splits
__device__ __half g_bias[(size_t)Bn * Hn * Nn * Nn]; // 134MB, log2e-scaled

#define SCALEQ 0.25506807163967554f   // 1/sqrt(32) * log2e
#define LOG2E  1.4426950408889634f

__device__ __forceinline__ float ex2(float x) {
    float y;
    asm("ex2.approx.f32 %0, %1;" : "=f"(y) : "f"(x));
    return y;
}
__device__ __forceinline__ uint32_t bits2(__nv_bfloat162 v) {
    return *reinterpret_cast<uint32_t*>(&v);
}
__device__ __forceinline__ uint2 pack4bf(float a, float b, float c, float d) {
    uint2 r;
    r.x = bits2(__floats2bfloat162_rn(a, b));
    r.y = bits2(__floats2bfloat162_rn(c, d));
    return r;
}
__device__ __forceinline__ void split2(float a, float b, uint32_t& h, uint32_t& l) {
    __nv_bfloat162 hp = __floats2bfloat162_rn(a, b);
    h = bits2(hp);
    l = bits2(__floats2bfloat162_rn(a - __low2float(hp), b - __high2float(hp)));
}

#define MMA(c, a, b0, b1)                                                     \
    asm volatile("mma.sync.aligned.m16n8k16.row.col.f32.bf16.bf16.f32 "       \
        "{%0,%1,%2,%3}, {%4,%5,%6,%7}, {%8,%9}, {%0,%1,%2,%3};"               \
        : "+f"((c)[0]), "+f"((c)[1]), "+f"((c)[2]), "+f"((c)[3])              \
        : "r"((a)[0]), "r"((a)[1]), "r"((a)[2]), "r"((a)[3]), "r"(b0), "r"(b1))

// ============================================================================
// convert x -> bf16 hi/lo
// ============================================================================
__global__ __launch_bounds__(256)
void convert_x(const float* __restrict__ x)
{
    int i = blockIdx.x * 256 + threadIdx.x;   // per float4
    float4 v = ((const float4*)x)[i];
    float f[4] = {v.x, v.y, v.z, v.w};
    float hi[4], lo[4];
#pragma unroll
    for (int t = 0; t < 4; t++) {
        hi[t] = __bfloat162float(__float2bfloat16_rn(f[t]));
        lo[t] = f[t] - hi[t];
    }
    ((uint2*)g_xhi)[i] = pack4bf(hi[0], hi[1], hi[2], hi[3]);
    ((uint2*)g_xlo)[i] = pack4bf(lo[0], lo[1], lo[2], lo[3]);
}

// ============================================================================
// convert W -> W^T bf16 hi/lo (32x32 tiles)
// ============================================================================
__global__ __launch_bounds__(256)
void convert_wt(const float* __restrict__ W0, const float* __restrict__ W1,
                const float* __restrict__ W2, const float* __restrict__ W3)
{
    __shared__ float T[32][33];
    const int z = blockIdx.x >> 6;
    const int tile = blockIdx.x & 63;
    const int k0 = (tile >> 3) * 32;
    const int n0 = (tile & 7) * 32;
    const float* W = (z == 0) ? W0 : (z == 1) ? W1 : (z == 2) ? W2 : W3;
    const int tid = threadIdx.x;
    {
        int r = tid >> 3, c4 = tid & 7;
        float4 v = *(const float4*)&W[(k0 + r) * En + n0 + c4 * 4];
        T[r][c4 * 4 + 0] = v.x; T[r][c4 * 4 + 1] = v.y;
        T[r][c4 * 4 + 2] = v.z; T[r][c4 * 4 + 3] = v.w;
    }
    __syncthreads();
    {
        int r = tid >> 3, c4 = tid & 7;
        float f[4], hi[4], lo[4];
#pragma unroll
        for (int u = 0; u < 4; u++) {
            f[u] = T[c4 * 4 + u][r];
            hi[u] = __bfloat162float(__float2bfloat16_rn(f[u]));
            lo[u] = f[u] - hi[u];
        }
        int off = z * En * En + (n0 + r) * En + k0 + c4 * 4;
        *(uint2*)&g_wthi[off] = pack4bf(hi[0], hi[1], hi[2], hi[3]);
        *(uint2*)&g_wtlo[off] = pack4bf(lo[0], lo[1], lo[2], lo[3]);
    }
}

// ============================================================================
// tensor-core split-bf16 GEMM: C[128x64] tile of A[8192x256] @ B^T.
// MODE 0: QKV (z=blockIdx.z; epilogue -> split Q(scaled)/K, fp32 V)
// MODE 1: out-proj (A=g_chi/clo, W slot 3; epilogue -> +bo +x -> out)
// ============================================================================
#define GA_HI 0
#define GA_LO 2560
#define GB_HI 5120
#define GB_LO 6400
#define GSM_W 7680

template <int MODE>
__global__ __launch_bounds__(256)
void gemm_tc(const float* __restrict__ bias0, const float* __restrict__ bias1,
             const float* __restrict__ bias2,
             const float* __restrict__ X, float* __restrict__ OutR)
{
    __shared__ __align__(16) uint32_t S[GSM_W];
    const int tid = threadIdx.x;
    const int w = tid >> 5, lane = tid & 31;
    const int g = lane >> 2, t = lane & 3;
    const int row0 = blockIdx.y * 128;
    const int col0 = blockIdx.x * 64;
    const int z = (MODE == 0) ? blockIdx.z : 3;

    const uint4* ah4 = (const uint4*)((MODE == 0) ? g_xhi : g_chi);
    const uint4* al4 = (const uint4*)((MODE == 0) ? g_xlo : g_clo);
    const uint4* bh4 = (const uint4*)(g_wthi + z * En * En);
    const uint4* bl4 = (const uint4*)(g_wtlo + z * En * En);

    float c_[8][4] = {};

    const int a_row = tid >> 1;
    const int a_c4 = (tid & 1) * 2;
    const int b_row = tid >> 2;
    const int b_c4 = tid & 3;

    for (int kc = 0; kc < 8; kc++) {
        {
            size_t si = (size_t)(row0 + a_row) * 32 + kc * 4 + a_c4;
            *(uint4*)&S[GA_HI + a_row * 20 + a_c4 * 4] = ah4[si];
            *(uint4*)&S[GA_HI + a_row * 20 + (a_c4 + 1) * 4] = ah4[si + 1];
            *(uint4*)&S[GA_LO + a_row * 20 + a_c4 * 4] = al4[si];
            *(uint4*)&S[GA_LO + a_row * 20 + (a_c4 + 1) * 4] = al4[si + 1];
        }
        {
            size_t si = (size_t)(col0 + b_row) * 32 + kc * 4 + b_c4;
            *(uint4*)&S[GB_HI + b_row * 20 + b_c4 * 4] = bh4[si];
            *(uint4*)&S[GB_LO + b_row * 20 + b_c4 * 4] = bl4[si];
        }
        __syncthreads();
#pragma unroll
        for (int kt = 0; kt < 2; kt++) {
            const int aw = (w * 16 + g) * 20 + kt * 8 + t;
            uint32_t ah[4], al[4];
            ah[0] = S[GA_HI + aw];       ah[1] = S[GA_HI + aw + 160];
            ah[2] = S[GA_HI + aw + 4];   ah[3] = S[GA_HI + aw + 164];
            al[0] = S[GA_LO + aw];       al[1] = S[GA_LO + aw + 160];
            al[2] = S[GA_LO + aw + 4];   al[3] = S[GA_LO + aw + 164];
#pragma unroll
            for (int nt = 0; nt < 8; nt++) {
                const int kw = (nt * 8 + g) * 20 + kt * 8 + t;
                uint32_t b0h = S[GB_HI + kw], b1h = S[GB_HI + kw + 4];
                uint32_t b0l = S[GB_LO + kw], b1l = S[GB_LO + kw + 4];
                MMA(c_[nt], ah, b0h, b1h);
                MMA(c_[nt], al, b0h, b1h);
                MMA(c_[nt], ah, b0l, b1l);
            }
        }
        __syncthreads();
    }

    const int m = row0 + w * 16 + g;
    if (MODE == 0) {
        const float* bias = (z == 0) ? bias0 : (z == 1) ? bias1 : bias2;
        const int b = m >> 10, n = m & 1023;
#pragma unroll
        for (int nt = 0; nt < 8; nt++) {
            int col = col0 + nt * 8 + 2 * t;
            float bz0 = bias[col], bz1 = bias[col + 1];
            float v0 = c_[nt][0] + bz0, v1 = c_[nt][1] + bz1;
            float v2 = c_[nt][2] + bz0, v3 = c_[nt][3] + bz1;
            int h = col >> 5, dd = col & 31;
            size_t oA = ((size_t)(b * Hn + h) * Nn + n) * Dn + dd;
            size_t oB = oA + 8 * Dn;
            if (z == 0) {
                v0 *= SCALEQ; v1 *= SCALEQ; v2 *= SCALEQ; v3 *= SCALEQ;
                uint32_t hA, lA, hB, lB;
                split2(v0, v1, hA, lA);
                split2(v2, v3, hB, lB);
                *(uint32_t*)&g_qhi[oA] = hA; *(uint32_t*)&g_qlo[oA] = lA;
                *(uint32_t*)&g_qhi[oB] = hB; *(uint32_t*)&g_qlo[oB] = lB;
            } else if (z == 1) {
                uint32_t hA, lA, hB, lB;
                split2(v0, v1, hA, lA);
                split2(v2, v3, hB, lB);
                *(uint32_t*)&g_khi[oA] = hA; *(uint32_t*)&g_klo[oA] = lA;
                *(uint32_t*)&g_khi[oB] = hB; *(uint32_t*)&g_klo[oB] = lB;
            } else {
                float2 p0 = {v0, v1}, p1 = {v2, v3};
                *(float2*)&d_V[oA] = p0;
                *(float2*)&d_V[oB] = p1;
            }
        }
    } else {
#pragma unroll
        for (int nt = 0; nt < 8; nt++) {
            int col = col0 + nt * 8 + 2 * t;
            float bz0 = bias0[col], bz1 = bias0[col + 1];
            float2 xA = *(const float2*)&X[(size_t)m * En + col];
            float2 xB = *(const float2*)&X[(size_t)(m + 8) * En + col];
            float2 oA = {c_[nt][0] + bz0 + xA.x, c_[nt][1] + bz1 + xA.y};
            float2 oB = {c_[nt][2] + bz0 + xB.x, c_[nt][3] + bz1 + xB.y};
            *(float2*)&OutR[(size_t)m * En + col] = oA;
            *(float2*)&OutR[(size_t)(m + 8) * En + col] = oB;
        }
    }
}

// ============================================================================
// transpose V to [B,H,D,N] + split
// ============================================================================
__global__ __launch_bounds__(256)
void transpose_v()
{
    __shared__ float T[32][36];
    const int tid = threadIdx.x;
    const int blk = blockIdx.x;
    const int bh = blk >> 5, jt = blk & 31;
    const int j0 = jt * 32;
    {
        int r = tid >> 3, c = tid & 7;
        float4 v = *(const float4*)&d_V[(bh * Nn + j0 + r) * Dn + c * 4];
        *(float4*)&T[r][c * 4] = v;
    }
    __syncthreads();
    {
        int d = tid >> 3, c = tid & 7;
        float f[4], hi[4], lo[4];
#pragma unroll
        for (int u = 0; u < 4; u++) {
            f[u] = T[c * 4 + u][d];
            hi[u] = __bfloat162float(__float2bfloat16_rn(f[u]));
            lo[u] = f[u] - hi[u];
        }
        int off = (bh * Dn + d) * Nn + j0 + c * 4;
        *(uint2*)&g_vthi[off] = pack4bf(hi[0], hi[1], hi[2], hi[3]);
        *(uint2*)&g_vtlo[off] = pack4bf(lo[0], lo[1], lo[2], lo[3]);
    }
}

// ============================================================================
// bias precompute  bias[b,h,i,j] = (adj[b,i,j,:]@Wa[:,h] + ba[h])*log2e  (fp16)
// ============================================================================
__global__ __launch_bounds__(256)
void bias_pre(const float* __restrict__ adj, const float* __restrict__ Wa,
              const float* __restrict__ ba)
{
    const int tid = threadIdx.x;
    const int b = blockIdx.x >> 10;
    const int i = blockIdx.x & 1023;
    float w2[Cn][Hn], off[Hn];
#pragma unroll
    for (int h = 0; h < Hn; h++) {
        off[h] = ba[h] * LOG2E;
#pragma unroll
        for (int c = 0; c < Cn; c++) w2[c][h] = Wa[c * Hn + h] * LOG2E;
    }
    const float4* a4 = (const float4*)&adj[(size_t)(b * Nn + i) * Nn * Cn];
#pragma unroll
    for (int r = 0; r < 2; r++) {
        int j = (tid + r * 256) * 2;
        float4 x0 = a4[j];
        float4 x1 = a4[j + 1];
#pragma unroll
        for (int h = 0; h < Hn; h++) {
            float v0 = off[h] + x0.x * w2[0][h] + x0.y * w2[1][h] + x0.z * w2[2][h] + x0.w * w2[3][h];
            float v1 = off[h] + x1.x * w2[0][h] + x1.y * w2[1][h] + x1.z * w2[2][h] + x1.w * w2[3][h];
            __half2 hv = __floats2half2_rn(v0, v1);
            *(__half2*)&g_bias[((size_t)(b * Hn + h) * Nn + i) * Nn + j] = hv;
        }
    }
}

// ============================================================================
// tensor-core flash attention.  NO online max (scores bounded, log2 domain);
// bias read directly from gmem in C-fragment layout (no smem staging).
// ============================================================================
#define KHI_W 0
#define KLO_W 1280
#define VTHI_W 2560
#define VTLO_W 3712
#define SMEM_W 4864

__global__ __launch_bounds__(256)
void attn_tc()
{
    __shared__ __align__(16) uint32_t S[SMEM_W];
    const int tid = threadIdx.x;
    const int w = tid >> 5, lane = tid & 31;
    const int g = lane >> 2, t = lane & 3;
    const int i0 = blockIdx.x * 128;
    const int bh = blockIdx.z * Hn + blockIdx.y;

    const uint32_t* q32h = (const uint32_t*)g_qhi;
    const uint32_t* q32l = (const uint32_t*)g_qlo;
    const int rowA = bh * Nn + i0 + w * 16 + g;
    const int rowB = rowA + 8;
    uint32_t aQh[2][4], aQl[2][4];
#pragma unroll
    for (int kt = 0; kt < 2; kt++) {
        aQh[kt][0] = q32h[rowA * 16 + kt * 8 + t];
        aQh[kt][1] = q32h[rowB * 16 + kt * 8 + t];
        aQh[kt][2] = q32h[rowA * 16 + kt * 8 + 4 + t];
        aQh[kt][3] = q32h[rowB * 16 + kt * 8 + 4 + t];
        aQl[kt][0] = q32l[rowA * 16 + kt * 8 + t];
        aQl[kt][1] = q32l[rowB * 16 + kt * 8 + t];
        aQl[kt][2] = q32l[rowA * 16 + kt * 8 + 4 + t];
        aQl[kt][3] = q32l[rowB * 16 + kt * 8 + 4 + t];
    }

    float O[4][4] = {};
    float lA = 0.f, lB = 0.f;

    const uint4* kh4 = (const uint4*)g_khi;
    const uint4* kl4 = (const uint4*)g_klo;
    const uint4* vh4 = (const uint4*)g_vthi;
    const uint4* vl4 = (const uint4*)g_vtlo;
    // bias rows for this thread's two fragment rows (half2 units)
    const uint32_t* biasA = (const uint32_t*)&g_bias[((size_t)rowA) * Nn];
    const uint32_t* biasB = (const uint32_t*)&g_bias[((size_t)rowB) * Nn];

    for (int jt = 0; jt < 16; jt++) {
        const int j0 = jt * 64;
        {
            int row = tid >> 2, c = tid & 3;
            uint4 v1 = kh4[(bh * Nn + j0 + row) * 4 + c];
            uint4 v2 = kl4[(bh * Nn + j0 + row) * 4 + c];
            *(uint4*)&S[KHI_W + row * 20 + c * 4] = v1;
            *(uint4*)&S[KLO_W + row * 20 + c * 4] = v2;
        }
        {
            int d = tid >> 3, c = tid & 7;
            uint4 v1 = vh4[(bh * Dn + d) * 128 + jt * 8 + c];
            uint4 v2 = vl4[(bh * Dn + d) * 128 + jt * 8 + c];
            *(uint4*)&S[VTHI_W + d * 36 + c * 4] = v1;
            *(uint4*)&S[VTLO_W + d * 36 + c * 4] = v2;
        }
        __syncthreads();

        // ---- QK^T (3-term split) ----
        float c_[8][4] = {};
#pragma unroll
        for (int nt = 0; nt < 8; nt++) {
#pragma unroll
            for (int kt = 0; kt < 2; kt++) {
                int kw = (nt * 8 + g) * 20 + kt * 8 + t;
                uint32_t bh0 = S[KHI_W + kw], bh1 = S[KHI_W + kw + 4];
                uint32_t bl0 = S[KLO_W + kw], bl1 = S[KLO_W + kw + 4];
                MMA(c_[nt], aQh[kt], bh0, bh1);
                MMA(c_[nt], aQl[kt], bh0, bh1);
                MMA(c_[nt], aQh[kt], bl0, bl1);
            }
        }
        // ---- + bias direct from gmem (half2 per row-pair) ----
#pragma unroll
        for (int nt = 0; nt < 8; nt++) {
            uint32_t u0 = biasA[(j0 >> 1) + nt * 4 + t];
            uint32_t u1 = biasB[(j0 >> 1) + nt * 4 + t];
            __half2 h0 = *(__half2*)&u0;
            __half2 h1 = *(__half2*)&u1;
            c_[nt][0] += __low2float(h0);
            c_[nt][1] += __high2float(h0);
            c_[nt][2] += __low2float(h1);
            c_[nt][3] += __high2float(h1);
        }
        // ---- P = exp2(s) (no max subtraction; scores bounded) ----
        uint32_t PH[8], PH2[8], PL[8], PL2[8];
#pragma unroll
        for (int nt = 0; nt < 8; nt++) {
            float p0 = ex2(c_[nt][0]), p1 = ex2(c_[nt][1]);
            float p2 = ex2(c_[nt][2]), p3 = ex2(c_[nt][3]);
            lA += p0 + p1;
            lB += p2 + p3;
            __nv_bfloat162 x01 = __floats2bfloat162_rn(p0, p1);
            __nv_bfloat162 x23 = __floats2bfloat162_rn(p2, p3);
            PH[nt]  = bits2(x01);
            PH2[nt] = bits2(x23);
            PL[nt]  = bits2(__floats2bfloat162_rn(p0 - __low2float(x01), p1 - __high2float(x01)));
            PL2[nt] = bits2(__floats2bfloat162_rn(p2 - __low2float(x23), p3 - __high2float(x23)));
        }
        // ---- PV (3-term split) ----
#pragma unroll
        for (int dnt = 0; dnt < 4; dnt++) {
#pragma unroll
            for (int u = 0; u < 4; u++) {
                int vw = (dnt * 8 + g) * 36 + u * 8 + t;
                uint32_t vh0 = S[VTHI_W + vw], vh1 = S[VTHI_W + vw + 4];
                uint32_t vl0 = S[VTLO_W + vw], vl1 = S[VTLO_W + vw + 4];
                uint32_t aP[4]  = {PH[2 * u], PH2[2 * u], PH[2 * u + 1], PH2[2 * u + 1]};
                uint32_t aPl[4] = {PL[2 * u], PL2[2 * u], PL[2 * u + 1], PL2[2 * u + 1]};
                MMA(O[dnt], aP, vh0, vh1);
                MMA(O[dnt], aPl, vh0, vh1);
                MMA(O[dnt], aP, vl0, vl1);
            }
        }
        __syncthreads();
    }

    lA += __shfl_xor_sync(0xffffffffu, lA, 1);
    lA += __shfl_xor_sync(0xffffffffu, lA, 2);
    lB += __shfl_xor_sync(0xffffffffu, lB, 1);
    lB += __shfl_xor_sync(0xffffffffu, lB, 2);
    const float iA = 1.f / lA, iB = 1.f / lB;

    // epilogue: write ctx split bf16 row-major [b][n][h*32+d]
    const int b = bh >> 3, h = bh & 7;
    const int nA = rowA & (Nn - 1);
    const size_t baseA = ((size_t)b * Nn + nA) * En + h * Dn;
    const size_t baseB = baseA + 8 * En;
#pragma unroll
    for (int dnt = 0; dnt < 4; dnt++) {
        int dd = dnt * 8 + 2 * t;
        uint32_t hA, lA2, hB, lB2;
        split2(O[dnt][0] * iA, O[dnt][1] * iA, hA, lA2);
        split2(O[dnt][2] * iB, O[dnt][3] * iB, hB, lB2);
        *(uint32_t*)&g_chi[baseA + dd] = hA;
        *(uint32_t*)&g_clo[baseA + dd] = lA2;
        *(uint32_t*)&g_chi[baseB + dd] = hB;
        *(uint32_t*)&g_clo[baseB + dd] = lB2;
    }
}

// ============================================================================
extern "C" void kernel_launch(void* const* d_in, const int* in_sizes, int n_in,
                              void* d_out, int out_size)
{
    const float* x   = (const float*)d_in[0];
    const float* adj = (const float*)d_in[1];
    const float* Wq  = (const float*)d_in[2];
    const float* bq  = (const float*)d_in[3];
    const float* Wk  = (const float*)d_in[4];
    const float* bk  = (const float*)d_in[5];
    const float* Wv  = (const float*)d_in[6];
    const float* bv  = (const float*)d_in[7];
    const float* Wo  = (const float*)d_in[8];
    const float* bo  = (const float*)d_in[9];
    const float* Wa  = (const float*)d_in[10];
    const float* ba  = (const float*)d_in[11];
    float* out = (float*)d_out;

    convert_x<<<(Bn * Nn * En / 4) / 256, 256>>>(x);
    convert_wt<<<4 * 64, 256>>>(Wq, Wk, Wv, Wo);

    dim3 gq(En / 64, (Bn * Nn) / 128, 3);
    gemm_tc<0><<<gq, 256>>>(bq, bk, bv, nullptr, nullptr);

    transpose_v<<<Bn * Hn * (Nn / 32), 256>>>();
    bias_pre<<<Bn * Nn, 256>>>(adj, Wa, ba);

    dim3 ga(Nn / 128, Hn, Bn);
    attn_tc<<<ga, 256>>>();

    dim3 go(En / 64, (Bn * Nn) / 128);
    gemm_tc<1><<<go, 256>>>(bo, bo, bo, x, out);
}

// round 8
// speedup vs baseline: 2.3415x; 1.6229x over previous
#include <cuda_runtime.h>
#include <cuda_bf16.h>
#include <cuda_fp16.h>
#include <cstdint>

#define Bn 8
#define Nn 1024
#define En 256
#define Hn 8
#define Dn 32
#define Cn 4

#define QSZ (Bn * Hn * Nn * Dn)            // 2M elems
__device__ float d_V[QSZ];
__device__ __half g_xh[Bn * Nn * En];
__device__ __half g_qh[QSZ];
__device__ __half g_kh[QSZ];
__device__ __half g_vth[QSZ];              // [B,H,D,N]
__device__ __half g_ch[Bn * Nn * En];      // ctx row-major
__device__ __half g_wth[4 * En * En];      // W^T: q,k,v,o
__device__ __half g_bias[(size_t)Bn * Hn * Nn * Nn]; // 134MB, log2e-scaled

#define SCALEQ 0.25506807163967554f   // 1/sqrt(32) * log2e
#define LOG2E  1.4426950408889634f

__device__ __forceinline__ float ex2(float x) {
    float y;
    asm("ex2.approx.f32 %0, %1;" : "=f"(y) : "f"(x));
    return y;
}
__device__ __forceinline__ uint32_t bitsh2(__half2 v) {
    return *reinterpret_cast<uint32_t*>(&v);
}
__device__ __forceinline__ uint2 pack4h(float a, float b, float c, float d) {
    uint2 r;
    r.x = bitsh2(__floats2half2_rn(a, b));
    r.y = bitsh2(__floats2half2_rn(c, d));
    return r;
}

#define MMAH(c, a, b0, b1)                                                    \
    asm volatile("mma.sync.aligned.m16n8k16.row.col.f32.f16.f16.f32 "         \
        "{%0,%1,%2,%3}, {%4,%5,%6,%7}, {%8,%9}, {%0,%1,%2,%3};"               \
        : "+f"((c)[0]), "+f"((c)[1]), "+f"((c)[2]), "+f"((c)[3])              \
        : "r"((a)[0]), "r"((a)[1]), "r"((a)[2]), "r"((a)[3]), "r"(b0), "r"(b1))

// ============================================================================
// convert x -> fp16
// ============================================================================
__global__ __launch_bounds__(256)
void convert_x(const float* __restrict__ x)
{
    int i = blockIdx.x * 256 + threadIdx.x;   // per float4
    float4 v = ((const float4*)x)[i];
    ((uint2*)g_xh)[i] = pack4h(v.x, v.y, v.z, v.w);
}

// ============================================================================
// convert W -> W^T fp16 (32x32 tiles)
// ============================================================================
__global__ __launch_bounds__(256)
void convert_wt(const float* __restrict__ W0, const float* __restrict__ W1,
                const float* __restrict__ W2, const float* __restrict__ W3)
{
    __shared__ float T[32][33];
    const int z = blockIdx.x >> 6;
    const int tile = blockIdx.x & 63;
    const int k0 = (tile >> 3) * 32;
    const int n0 = (tile & 7) * 32;
    const float* W = (z == 0) ? W0 : (z == 1) ? W1 : (z == 2) ? W2 : W3;
    const int tid = threadIdx.x;
    {
        int r = tid >> 3, c4 = tid & 7;
        float4 v = *(const float4*)&W[(k0 + r) * En + n0 + c4 * 4];
        T[r][c4 * 4 + 0] = v.x; T[r][c4 * 4 + 1] = v.y;
        T[r][c4 * 4 + 2] = v.z; T[r][c4 * 4 + 3] = v.w;
    }
    __syncthreads();
    {
        int r = tid >> 3, c4 = tid & 7;
        int off = z * En * En + (n0 + r) * En + k0 + c4 * 4;
        *(uint2*)&g_wth[off] = pack4h(T[c4 * 4 + 0][r], T[c4 * 4 + 1][r],
                                      T[c4 * 4 + 2][r], T[c4 * 4 + 3][r]);
    }
}

// ============================================================================
// fp16 tensor-core GEMM: C[128x64] tile of A[8192x256] @ B^T (single term).
// MODE 0: QKV (z=blockIdx.z; epilogue -> fp16 Q(scaled)/K, fp32 V)
// MODE 1: out-proj (A=g_ch, W slot 3; epilogue -> +bo +x -> out fp32)
// ============================================================================
#define GA_W 0
#define GB_W 2560
#define GSM_W 3840

template <int MODE>
__global__ __launch_bounds__(256)
void gemm_tc(const float* __restrict__ bias0, const float* __restrict__ bias1,
             const float* __restrict__ bias2,
             const float* __restrict__ X, float* __restrict__ OutR)
{
    __shared__ __align__(16) uint32_t S[GSM_W];
    const int tid = threadIdx.x;
    const int w = tid >> 5, lane = tid & 31;
    const int g = lane >> 2, t = lane & 3;
    const int row0 = blockIdx.y * 128;
    const int col0 = blockIdx.x * 64;
    const int z = (MODE == 0) ? blockIdx.z : 3;

    const uint4* a4p = (const uint4*)((MODE == 0) ? g_xh : g_ch);
    const uint4* b4p = (const uint4*)(g_wth + z * En * En);

    float c_[8][4] = {};

    const int a_row = tid >> 1;          // 0..127
    const int a_c4 = (tid & 1) * 2;      // uint4 col 0/2
    const int b_row = tid >> 2;          // 0..63
    const int b_c4 = tid & 3;

    for (int kc = 0; kc < 8; kc++) {
        {
            size_t si = (size_t)(row0 + a_row) * 32 + kc * 4 + a_c4;  // row pitch 32 uint4
            *(uint4*)&S[GA_W + a_row * 20 + a_c4 * 4] = a4p[si];
            *(uint4*)&S[GA_W + a_row * 20 + (a_c4 + 1) * 4] = a4p[si + 1];
        }
        {
            size_t si = (size_t)(col0 + b_row) * 32 + kc * 4 + b_c4;
            *(uint4*)&S[GB_W + b_row * 20 + b_c4 * 4] = b4p[si];
        }
        __syncthreads();
#pragma unroll
        for (int kt = 0; kt < 2; kt++) {
            const int aw = (w * 16 + g) * 20 + kt * 8 + t;
            uint32_t a[4];
            a[0] = S[GA_W + aw];       a[1] = S[GA_W + aw + 160];
            a[2] = S[GA_W + aw + 4];   a[3] = S[GA_W + aw + 164];
#pragma unroll
            for (int nt = 0; nt < 8; nt++) {
                const int kw = (nt * 8 + g) * 20 + kt * 8 + t;
                MMAH(c_[nt], a, S[GB_W + kw], S[GB_W + kw + 4]);
            }
        }
        __syncthreads();
    }

    const int m = row0 + w * 16 + g;
    if (MODE == 0) {
        const float* bias = (z == 0) ? bias0 : (z == 1) ? bias1 : bias2;
        const int b = m >> 10, n = m & 1023;
#pragma unroll
        for (int nt = 0; nt < 8; nt++) {
            int col = col0 + nt * 8 + 2 * t;
            float bz0 = bias[col], bz1 = bias[col + 1];
            float v0 = c_[nt][0] + bz0, v1 = c_[nt][1] + bz1;
            float v2 = c_[nt][2] + bz0, v3 = c_[nt][3] + bz1;
            int h = col >> 5, dd = col & 31;
            size_t oA = ((size_t)(b * Hn + h) * Nn + n) * Dn + dd;
            size_t oB = oA + 8 * Dn;
            if (z == 0) {
                v0 *= SCALEQ; v1 *= SCALEQ; v2 *= SCALEQ; v3 *= SCALEQ;
                *(uint32_t*)&g_qh[oA] = bitsh2(__floats2half2_rn(v0, v1));
                *(uint32_t*)&g_qh[oB] = bitsh2(__floats2half2_rn(v2, v3));
            } else if (z == 1) {
                *(uint32_t*)&g_kh[oA] = bitsh2(__floats2half2_rn(v0, v1));
                *(uint32_t*)&g_kh[oB] = bitsh2(__floats2half2_rn(v2, v3));
            } else {
                float2 p0 = {v0, v1}, p1 = {v2, v3};
                *(float2*)&d_V[oA] = p0;
                *(float2*)&d_V[oB] = p1;
            }
        }
    } else {
#pragma unroll
        for (int nt = 0; nt < 8; nt++) {
            int col = col0 + nt * 8 + 2 * t;
            float bz0 = bias0[col], bz1 = bias0[col + 1];
            float2 xA = *(const float2*)&X[(size_t)m * En + col];
            float2 xB = *(const float2*)&X[(size_t)(m + 8) * En + col];
            float2 oA = {c_[nt][0] + bz0 + xA.x, c_[nt][1] + bz1 + xA.y};
            float2 oB = {c_[nt][2] + bz0 + xB.x, c_[nt][3] + bz1 + xB.y};
            *(float2*)&OutR[(size_t)m * En + col] = oA;
            *(float2*)&OutR[(size_t)(m + 8) * En + col] = oB;
        }
    }
}

// ============================================================================
// transpose V to [B,H,D,N] fp16
// ============================================================================
__global__ __launch_bounds__(256)
void transpose_v()
{
    __shared__ float T[32][36];
    const int tid = threadIdx.x;
    const int blk = blockIdx.x;
    const int bh = blk >> 5, jt = blk & 31;
    const int j0 = jt * 32;
    {
        int r = tid >> 3, c = tid & 7;
        float4 v = *(const float4*)&d_V[(bh * Nn + j0 + r) * Dn + c * 4];
        *(float4*)&T[r][c * 4] = v;
    }
    __syncthreads();
    {
        int d = tid >> 3, c = tid & 7;
        int off = (bh * Dn + d) * Nn + j0 + c * 4;
        *(uint2*)&g_vth[off] = pack4h(T[c * 4 + 0][d], T[c * 4 + 1][d],
                                      T[c * 4 + 2][d], T[c * 4 + 3][d]);
    }
}

// ============================================================================
// bias precompute  bias[b,h,i,j] = (adj[b,i,j,:]@Wa[:,h] + ba[h])*log2e  (fp16)
// ============================================================================
__global__ __launch_bounds__(256)
void bias_pre(const float* __restrict__ adj, const float* __restrict__ Wa,
              const float* __restrict__ ba)
{
    const int tid = threadIdx.x;
    const int b = blockIdx.x >> 10;
    const int i = blockIdx.x & 1023;
    float w2[Cn][Hn], off[Hn];
#pragma unroll
    for (int h = 0; h < Hn; h++) {
        off[h] = ba[h] * LOG2E;
#pragma unroll
        for (int c = 0; c < Cn; c++) w2[c][h] = Wa[c * Hn + h] * LOG2E;
    }
    const float4* a4 = (const float4*)&adj[(size_t)(b * Nn + i) * Nn * Cn];
#pragma unroll
    for (int r = 0; r < 2; r++) {
        int j = (tid + r * 256) * 2;
        float4 x0 = a4[j];
        float4 x1 = a4[j + 1];
#pragma unroll
        for (int h = 0; h < Hn; h++) {
            float v0 = off[h] + x0.x * w2[0][h] + x0.y * w2[1][h] + x0.z * w2[2][h] + x0.w * w2[3][h];
            float v1 = off[h] + x1.x * w2[0][h] + x1.y * w2[1][h] + x1.z * w2[2][h] + x1.w * w2[3][h];
            __half2 hv = __floats2half2_rn(v0, v1);
            *(__half2*)&g_bias[((size_t)(b * Hn + h) * Nn + i) * Nn + j] = hv;
        }
    }
}

// ============================================================================
// fp16 tensor-core flash attention (single-term MMAs, no online max,
// bias staged through smem in R5-proven layout).
// ============================================================================
#define K_W 0
#define V_W 1280
#define BIAS_W 2432
#define SMEM_W 7040

__global__ __launch_bounds__(256)
void attn_tc()
{
    __shared__ __align__(16) uint32_t S[SMEM_W];
    const int tid = threadIdx.x;
    const int w = tid >> 5, lane = tid & 31;
    const int g = lane >> 2, t = lane & 3;
    const int i0 = blockIdx.x * 128;
    const int bh = blockIdx.z * Hn + blockIdx.y;

    const uint32_t* q32 = (const uint32_t*)g_qh;
    const int rowA = bh * Nn + i0 + w * 16 + g;
    const int rowB = rowA + 8;
    uint32_t aQ[2][4];
#pragma unroll
    for (int kt = 0; kt < 2; kt++) {
        aQ[kt][0] = q32[rowA * 16 + kt * 8 + t];
        aQ[kt][1] = q32[rowB * 16 + kt * 8 + t];
        aQ[kt][2] = q32[rowA * 16 + kt * 8 + 4 + t];
        aQ[kt][3] = q32[rowB * 16 + kt * 8 + 4 + t];
    }

    float O[4][4] = {};
    float lA = 0.f, lB = 0.f;

    const uint4* k4p = (const uint4*)g_kh;
    const uint4* v4p = (const uint4*)g_vth;
    const uint4* bg4 = (const uint4*)g_bias;

    for (int jt = 0; jt < 16; jt++) {
        const int j0 = jt * 64;
        // ---- stage K: 64 rows x 4 uint4 (32 fp16/row) ----
        {
            int row = tid >> 2, c = tid & 3;
            *(uint4*)&S[K_W + row * 20 + c * 4] = k4p[(bh * Nn + j0 + row) * 4 + c];
        }
        // ---- stage V^T: 32 d-rows x 8 uint4 (64 fp16/row) ----
        {
            int d = tid >> 3, c = tid & 7;
            *(uint4*)&S[V_W + d * 36 + c * 4] = v4p[(bh * Dn + d) * 128 + jt * 8 + c];
        }
        // ---- stage bias: 128 rows x 8 uint4 (64 fp16/row) ----
#pragma unroll
        for (int r = 0; r < 4; r++) {
            int idx = tid + r * 256;
            int row = idx >> 3, c = idx & 7;
            *(uint4*)&S[BIAS_W + row * 36 + c * 4] =
                bg4[((size_t)(bh * Nn) + i0 + row) * 128 + jt * 8 + c];
        }
        __syncthreads();

        // ---- QK^T (single fp16 term) ----
        float c_[8][4] = {};
#pragma unroll
        for (int nt = 0; nt < 8; nt++) {
#pragma unroll
            for (int kt = 0; kt < 2; kt++) {
                int kw = (nt * 8 + g) * 20 + kt * 8 + t;
                MMAH(c_[nt], aQ[kt], S[K_W + kw], S[K_W + kw + 4]);
            }
        }
        // ---- + bias from smem ----
        const int biA = (w * 16 + g) * 36;
        const int biB = (w * 16 + g + 8) * 36;
#pragma unroll
        for (int nt = 0; nt < 8; nt++) {
            uint32_t u0 = S[BIAS_W + biA + nt * 4 + t];
            uint32_t u1 = S[BIAS_W + biB + nt * 4 + t];
            __half2 h0 = *(__half2*)&u0;
            __half2 h1 = *(__half2*)&u1;
            c_[nt][0] += __low2float(h0);
            c_[nt][1] += __high2float(h0);
            c_[nt][2] += __low2float(h1);
            c_[nt][3] += __high2float(h1);
        }
        // ---- P = exp2(s) (no max; scores bounded), pack fp16 ----
        uint32_t PH[8], PH2[8];
#pragma unroll
        for (int nt = 0; nt < 8; nt++) {
            float p0 = ex2(c_[nt][0]), p1 = ex2(c_[nt][1]);
            float p2 = ex2(c_[nt][2]), p3 = ex2(c_[nt][3]);
            lA += p0 + p1;
            lB += p2 + p3;
            PH[nt]  = bitsh2(__floats2half2_rn(p0, p1));
            PH2[nt] = bitsh2(__floats2half2_rn(p2, p3));
        }
        // ---- PV (single fp16 term) ----
#pragma unroll
        for (int dnt = 0; dnt < 4; dnt++) {
#pragma unroll
            for (int u = 0; u < 4; u++) {
                int vw = (dnt * 8 + g) * 36 + u * 8 + t;
                uint32_t aP[4] = {PH[2 * u], PH2[2 * u], PH[2 * u + 1], PH2[2 * u + 1]};
                MMAH(O[dnt], aP, S[V_W + vw], S[V_W + vw + 4]);
            }
        }
        __syncthreads();
    }

    lA += __shfl_xor_sync(0xffffffffu, lA, 1);
    lA += __shfl_xor_sync(0xffffffffu, lA, 2);
    lB += __shfl_xor_sync(0xffffffffu, lB, 1);
    lB += __shfl_xor_sync(0xffffffffu, lB, 2);
    const float iA = 1.f / lA, iB = 1.f / lB;

    // epilogue: write ctx fp16 row-major [b][n][h*32+d]
    const int b = bh >> 3, h = bh & 7;
    const int nA = rowA & (Nn - 1);
    const size_t baseA = ((size_t)b * Nn + nA) * En + h * Dn;
    const size_t baseB = baseA + 8 * En;
#pragma unroll
    for (int dnt = 0; dnt < 4; dnt++) {
        int dd = dnt * 8 + 2 * t;
        *(uint32_t*)&g_ch[baseA + dd] = bitsh2(__floats2half2_rn(O[dnt][0] * iA, O[dnt][1] * iA));
        *(uint32_t*)&g_ch[baseB + dd] = bitsh2(__floats2half2_rn(O[dnt][2] * iB, O[dnt][3] * iB));
    }
}

// ============================================================================
extern "C" void kernel_launch(void* const* d_in, const int* in_sizes, int n_in,
                              void* d_out, int out_size)
{
    const float* x   = (const float*)d_in[0];
    const float* adj = (const float*)d_in[1];
    const float* Wq  = (const float*)d_in[2];
    const float* bq  = (const float*)d_in[3];
    const float* Wk  = (const float*)d_in[4];
    const float* bk  = (const float*)d_in[5];
    const float* Wv  = (const float*)d_in[6];
    const float* bv  = (const float*)d_in[7];
    const float* Wo  = (const float*)d_in[8];
    const float* bo  = (const float*)d_in[9];
    const float* Wa  = (const float*)d_in[10];
    const float* ba  = (const float*)d_in[11];
    float* out = (float*)d_out;

    convert_x<<<(Bn * Nn * En / 4) / 256, 256>>>(x);
    convert_wt<<<4 * 64, 256>>>(Wq, Wk, Wv, Wo);

    dim3 gq(En / 64, (Bn * Nn) / 128, 3);
    gemm_tc<0><<<gq, 256>>>(bq, bk, bv, nullptr, nullptr);

    transpose_v<<<Bn * Hn * (Nn / 32), 256>>>();
    bias_pre<<<Bn * Nn, 256>>>(adj, Wa, ba);

    dim3 ga(Nn / 128, Hn, Bn);
    attn_tc<<<ga, 256>>>();

    dim3 go(En / 64, (Bn * Nn) / 128);
    gemm_tc<1><<<go, 256>>>(bo, bo, bo, x, out);
}

// round 9
// speedup vs baseline: 2.3944x; 1.0226x over previous
#include <cuda_runtime.h>
#include <cuda_bf16.h>
#include <cuda_fp16.h>
#include <cstdint>

#define Bn 8
#define Nn 1024
#define En 256
#define Hn 8
#define Dn 32
#define Cn 4

#define QSZ (Bn * Hn * Nn * Dn)            // 2M elems
__device__ float d_V[QSZ];
__device__ __half g_xh[Bn * Nn * En];
__device__ __half g_qh[QSZ];
__device__ __half g_kh[QSZ];
__device__ __half g_vth[QSZ];              // [B,H,D,N]
__device__ __half g_ch[Bn * Nn * En];      // ctx row-major
__device__ __half g_wth[4 * En * En];      // W^T: q,k,v,o
__device__ __half g_bias[(size_t)Bn * Hn * Nn * Nn]; // 134MB, log2e-scaled

#define SCALEQ 0.25506807163967554f   // 1/sqrt(32) * log2e
#define LOG2E  1.4426950408889634f

__device__ __forceinline__ float ex2(float x) {
    float y;
    asm("ex2.approx.f32 %0, %1;" : "=f"(y) : "f"(x));
    return y;
}
__device__ __forceinline__ uint32_t bitsh2(__half2 v) {
    return *reinterpret_cast<uint32_t*>(&v);
}
__device__ __forceinline__ uint2 pack4h(float a, float b, float c, float d) {
    uint2 r;
    r.x = bitsh2(__floats2half2_rn(a, b));
    r.y = bitsh2(__floats2half2_rn(c, d));
    return r;
}

#define MMAH(c, a, b0, b1)                                                    \
    asm volatile("mma.sync.aligned.m16n8k16.row.col.f32.f16.f16.f32 "         \
        "{%0,%1,%2,%3}, {%4,%5,%6,%7}, {%8,%9}, {%0,%1,%2,%3};"               \
        : "+f"((c)[0]), "+f"((c)[1]), "+f"((c)[2]), "+f"((c)[3])              \
        : "r"((a)[0]), "r"((a)[1]), "r"((a)[2]), "r"((a)[3]), "r"(b0), "r"(b1))

// ============================================================================
// convert x -> fp16
// ============================================================================
__global__ __launch_bounds__(256)
void convert_x(const float* __restrict__ x)
{
    int i = blockIdx.x * 256 + threadIdx.x;   // per float4
    float4 v = ((const float4*)x)[i];
    ((uint2*)g_xh)[i] = pack4h(v.x, v.y, v.z, v.w);
}

// ============================================================================
// convert W -> W^T fp16 (32x32 tiles)
// ============================================================================
__global__ __launch_bounds__(256)
void convert_wt(const float* __restrict__ W0, const float* __restrict__ W1,
                const float* __restrict__ W2, const float* __restrict__ W3)
{
    __shared__ float T[32][33];
    const int z = blockIdx.x >> 6;
    const int tile = blockIdx.x & 63;
    const int k0 = (tile >> 3) * 32;
    const int n0 = (tile & 7) * 32;
    const float* W = (z == 0) ? W0 : (z == 1) ? W1 : (z == 2) ? W2 : W3;
    const int tid = threadIdx.x;
    {
        int r = tid >> 3, c4 = tid & 7;
        float4 v = *(const float4*)&W[(k0 + r) * En + n0 + c4 * 4];
        T[r][c4 * 4 + 0] = v.x; T[r][c4 * 4 + 1] = v.y;
        T[r][c4 * 4 + 2] = v.z; T[r][c4 * 4 + 3] = v.w;
    }
    __syncthreads();
    {
        int r = tid >> 3, c4 = tid & 7;
        int off = z * En * En + (n0 + r) * En + k0 + c4 * 4;
        *(uint2*)&g_wth[off] = pack4h(T[c4 * 4 + 0][r], T[c4 * 4 + 1][r],
                                      T[c4 * 4 + 2][r], T[c4 * 4 + 3][r]);
    }
}

// ============================================================================
// fp16 tensor-core GEMM: C[128x64] tile of A[8192x256] @ B^T (single term).
// MODE 0: QKV (z=blockIdx.z; epilogue -> fp16 Q(scaled)/K, fp32 V)
// MODE 1: out-proj (A=g_ch, W slot 3; epilogue -> +bo +x -> out fp32)
// ============================================================================
#define GA_W 0
#define GB_W 2560
#define GSM_W 3840

template <int MODE>
__global__ __launch_bounds__(256)
void gemm_tc(const float* __restrict__ bias0, const float* __restrict__ bias1,
             const float* __restrict__ bias2,
             const float* __restrict__ X, float* __restrict__ OutR)
{
    __shared__ __align__(16) uint32_t S[GSM_W];
    const int tid = threadIdx.x;
    const int w = tid >> 5, lane = tid & 31;
    const int g = lane >> 2, t = lane & 3;
    const int row0 = blockIdx.y * 128;
    const int col0 = blockIdx.x * 64;
    const int z = (MODE == 0) ? blockIdx.z : 3;

    const uint4* a4p = (const uint4*)((MODE == 0) ? g_xh : g_ch);
    const uint4* b4p = (const uint4*)(g_wth + z * En * En);

    float c_[8][4] = {};

    const int a_row = tid >> 1;          // 0..127
    const int a_c4 = (tid & 1) * 2;      // uint4 col 0/2
    const int b_row = tid >> 2;          // 0..63
    const int b_c4 = tid & 3;

    for (int kc = 0; kc < 8; kc++) {
        {
            size_t si = (size_t)(row0 + a_row) * 32 + kc * 4 + a_c4;  // row pitch 32 uint4
            *(uint4*)&S[GA_W + a_row * 20 + a_c4 * 4] = a4p[si];
            *(uint4*)&S[GA_W + a_row * 20 + (a_c4 + 1) * 4] = a4p[si + 1];
        }
        {
            size_t si = (size_t)(col0 + b_row) * 32 + kc * 4 + b_c4;
            *(uint4*)&S[GB_W + b_row * 20 + b_c4 * 4] = b4p[si];
        }
        __syncthreads();
#pragma unroll
        for (int kt = 0; kt < 2; kt++) {
            const int aw = (w * 16 + g) * 20 + kt * 8 + t;
            uint32_t a[4];
            a[0] = S[GA_W + aw];       a[1] = S[GA_W + aw + 160];
            a[2] = S[GA_W + aw + 4];   a[3] = S[GA_W + aw + 164];
#pragma unroll
            for (int nt = 0; nt < 8; nt++) {
                const int kw = (nt * 8 + g) * 20 + kt * 8 + t;
                MMAH(c_[nt], a, S[GB_W + kw], S[GB_W + kw + 4]);
            }
        }
        __syncthreads();
    }

    const int m = row0 + w * 16 + g;
    if (MODE == 0) {
        const float* bias = (z == 0) ? bias0 : (z == 1) ? bias1 : bias2;
        const int b = m >> 10, n = m & 1023;
#pragma unroll
        for (int nt = 0; nt < 8; nt++) {
            int col = col0 + nt * 8 + 2 * t;
            float bz0 = bias[col], bz1 = bias[col + 1];
            float v0 = c_[nt][0] + bz0, v1 = c_[nt][1] + bz1;
            float v2 = c_[nt][2] + bz0, v3 = c_[nt][3] + bz1;
            int h = col >> 5, dd = col & 31;
            size_t oA = ((size_t)(b * Hn + h) * Nn + n) * Dn + dd;
            size_t oB = oA + 8 * Dn;
            if (z == 0) {
                v0 *= SCALEQ; v1 *= SCALEQ; v2 *= SCALEQ; v3 *= SCALEQ;
                *(uint32_t*)&g_qh[oA] = bitsh2(__floats2half2_rn(v0, v1));
                *(uint32_t*)&g_qh[oB] = bitsh2(__floats2half2_rn(v2, v3));
            } else if (z == 1) {
                *(uint32_t*)&g_kh[oA] = bitsh2(__floats2half2_rn(v0, v1));
                *(uint32_t*)&g_kh[oB] = bitsh2(__floats2half2_rn(v2, v3));
            } else {
                float2 p0 = {v0, v1}, p1 = {v2, v3};
                *(float2*)&d_V[oA] = p0;
                *(float2*)&d_V[oB] = p1;
            }
        }
    } else {
#pragma unroll
        for (int nt = 0; nt < 8; nt++) {
            int col = col0 + nt * 8 + 2 * t;
            float bz0 = bias0[col], bz1 = bias0[col + 1];
            float2 xA = *(const float2*)&X[(size_t)m * En + col];
            float2 xB = *(const float2*)&X[(size_t)(m + 8) * En + col];
            float2 oA = {c_[nt][0] + bz0 + xA.x, c_[nt][1] + bz1 + xA.y};
            float2 oB = {c_[nt][2] + bz0 + xB.x, c_[nt][3] + bz1 + xB.y};
            *(float2*)&OutR[(size_t)m * En + col] = oA;
            *(float2*)&OutR[(size_t)(m + 8) * En + col] = oB;
        }
    }
}

// ============================================================================
// transpose V to [B,H,D,N] fp16
// ============================================================================
__global__ __launch_bounds__(256)
void transpose_v()
{
    __shared__ float T[32][36];
    const int tid = threadIdx.x;
    const int blk = blockIdx.x;
    const int bh = blk >> 5, jt = blk & 31;
    const int j0 = jt * 32;
    {
        int r = tid >> 3, c = tid & 7;
        float4 v = *(const float4*)&d_V[(bh * Nn + j0 + r) * Dn + c * 4];
        *(float4*)&T[r][c * 4] = v;
    }
    __syncthreads();
    {
        int d = tid >> 3, c = tid & 7;
        int off = (bh * Dn + d) * Nn + j0 + c * 4;
        *(uint2*)&g_vth[off] = pack4h(T[c * 4 + 0][d], T[c * 4 + 1][d],
                                      T[c * 4 + 2][d], T[c * 4 + 3][d]);
    }
}

// ============================================================================
// bias precompute  bias[b,h,i,j] = (adj[b,i,j,:]@Wa[:,h] + ba[h])*log2e  (fp16)
// ============================================================================
__global__ __launch_bounds__(256)
void bias_pre(const float* __restrict__ adj, const float* __restrict__ Wa,
              const float* __restrict__ ba)
{
    const int tid = threadIdx.x;
    const int b = blockIdx.x >> 10;
    const int i = blockIdx.x & 1023;
    float w2[Cn][Hn], off[Hn];
#pragma unroll
    for (int h = 0; h < Hn; h++) {
        off[h] = ba[h] * LOG2E;
#pragma unroll
        for (int c = 0; c < Cn; c++) w2[c][h] = Wa[c * Hn + h] * LOG2E;
    }
    const float4* a4 = (const float4*)&adj[(size_t)(b * Nn + i) * Nn * Cn];
#pragma unroll
    for (int r = 0; r < 2; r++) {
        int j = (tid + r * 256) * 2;
        float4 x0 = a4[j];
        float4 x1 = a4[j + 1];
#pragma unroll
        for (int h = 0; h < Hn; h++) {
            float v0 = off[h] + x0.x * w2[0][h] + x0.y * w2[1][h] + x0.z * w2[2][h] + x0.w * w2[3][h];
            float v1 = off[h] + x1.x * w2[0][h] + x1.y * w2[1][h] + x1.z * w2[2][h] + x1.w * w2[3][h];
            __half2 hv = __floats2half2_rn(v0, v1);
            *(__half2*)&g_bias[((size_t)(b * Hn + h) * Nn + i) * Nn + j] = hv;
        }
    }
}

// ============================================================================
// fp16 tensor-core flash attention (single-term MMAs, no online max,
// bias staged through smem).
// ============================================================================
#define K_W 0
#define V_W 1280
#define BIAS_W 2432
#define SMEM_W 7040

__global__ __launch_bounds__(256)
void attn_tc()
{
    __shared__ __align__(16) uint32_t S[SMEM_W];
    const int tid = threadIdx.x;
    const int w = tid >> 5, lane = tid & 31;
    const int g = lane >> 2, t = lane & 3;
    const int i0 = blockIdx.x * 128;
    const int bh = blockIdx.z * Hn + blockIdx.y;

    const uint32_t* q32 = (const uint32_t*)g_qh;
    const int rowA = bh * Nn + i0 + w * 16 + g;
    const int rowB = rowA + 8;
    uint32_t aQ[2][4];
#pragma unroll
    for (int kt = 0; kt < 2; kt++) {
        aQ[kt][0] = q32[rowA * 16 + kt * 8 + t];
        aQ[kt][1] = q32[rowB * 16 + kt * 8 + t];
        aQ[kt][2] = q32[rowA * 16 + kt * 8 + 4 + t];
        aQ[kt][3] = q32[rowB * 16 + kt * 8 + 4 + t];
    }

    float O[4][4] = {};
    float lA = 0.f, lB = 0.f;

    const uint4* k4p = (const uint4*)g_kh;
    const uint4* v4p = (const uint4*)g_vth;
    const uint4* bg4 = (const uint4*)g_bias;

    for (int jt = 0; jt < 16; jt++) {
        const int j0 = jt * 64;
        {
            int row = tid >> 2, c = tid & 3;
            *(uint4*)&S[K_W + row * 20 + c * 4] = k4p[(bh * Nn + j0 + row) * 4 + c];
        }
        {
            int d = tid >> 3, c = tid & 7;
            *(uint4*)&S[V_W + d * 36 + c * 4] = v4p[(bh * Dn + d) * 128 + jt * 8 + c];
        }
#pragma unroll
        for (int r = 0; r < 4; r++) {
            int idx = tid + r * 256;
            int row = idx >> 3, c = idx & 7;
            *(uint4*)&S[BIAS_W + row * 36 + c * 4] =
                bg4[((size_t)(bh * Nn) + i0 + row) * 128 + jt * 8 + c];
        }
        __syncthreads();

        float c_[8][4] = {};
#pragma unroll
        for (int nt = 0; nt < 8; nt++) {
#pragma unroll
            for (int kt = 0; kt < 2; kt++) {
                int kw = (nt * 8 + g) * 20 + kt * 8 + t;
                MMAH(c_[nt], aQ[kt], S[K_W + kw], S[K_W + kw + 4]);
            }
        }
        const int biA = (w * 16 + g) * 36;
        const int biB = (w * 16 + g + 8) * 36;
#pragma unroll
        for (int nt = 0; nt < 8; nt++) {
            uint32_t u0 = S[BIAS_W + biA + nt * 4 + t];
            uint32_t u1 = S[BIAS_W + biB + nt * 4 + t];
            __half2 h0 = *(__half2*)&u0;
            __half2 h1 = *(__half2*)&u1;
            c_[nt][0] += __low2float(h0);
            c_[nt][1] += __high2float(h0);
            c_[nt][2] += __low2float(h1);
            c_[nt][3] += __high2float(h1);
        }
        uint32_t PH[8], PH2[8];
#pragma unroll
        for (int nt = 0; nt < 8; nt++) {
            float p0 = ex2(c_[nt][0]), p1 = ex2(c_[nt][1]);
            float p2 = ex2(c_[nt][2]), p3 = ex2(c_[nt][3]);
            lA += p0 + p1;
            lB += p2 + p3;
            PH[nt]  = bitsh2(__floats2half2_rn(p0, p1));
            PH2[nt] = bitsh2(__floats2half2_rn(p2, p3));
        }
#pragma unroll
        for (int dnt = 0; dnt < 4; dnt++) {
#pragma unroll
            for (int u = 0; u < 4; u++) {
                int vw = (dnt * 8 + g) * 36 + u * 8 + t;
                uint32_t aP[4] = {PH[2 * u], PH2[2 * u], PH[2 * u + 1], PH2[2 * u + 1]};
                MMAH(O[dnt], aP, S[V_W + vw], S[V_W + vw + 4]);
            }
        }
        __syncthreads();
    }

    lA += __shfl_xor_sync(0xffffffffu, lA, 1);
    lA += __shfl_xor_sync(0xffffffffu, lA, 2);
    lB += __shfl_xor_sync(0xffffffffu, lB, 1);
    lB += __shfl_xor_sync(0xffffffffu, lB, 2);
    const float iA = 1.f / lA, iB = 1.f / lB;

    const int b = bh >> 3, h = bh & 7;
    const int nA = rowA & (Nn - 1);
    const size_t baseA = ((size_t)b * Nn + nA) * En + h * Dn;
    const size_t baseB = baseA + 8 * En;
#pragma unroll
    for (int dnt = 0; dnt < 4; dnt++) {
        int dd = dnt * 8 + 2 * t;
        *(uint32_t*)&g_ch[baseA + dd] = bitsh2(__floats2half2_rn(O[dnt][0] * iA, O[dnt][1] * iA));
        *(uint32_t*)&g_ch[baseB + dd] = bitsh2(__floats2half2_rn(O[dnt][2] * iB, O[dnt][3] * iB));
    }
}

// ============================================================================
extern "C" void kernel_launch(void* const* d_in, const int* in_sizes, int n_in,
                              void* d_out, int out_size)
{
    const float* x   = (const float*)d_in[0];
    const float* adj = (const float*)d_in[1];
    const float* Wq  = (const float*)d_in[2];
    const float* bq  = (const float*)d_in[3];
    const float* Wk  = (const float*)d_in[4];
    const float* bk  = (const float*)d_in[5];
    const float* Wv  = (const float*)d_in[6];
    const float* bv  = (const float*)d_in[7];
    const float* Wo  = (const float*)d_in[8];
    const float* bo  = (const float*)d_in[9];
    const float* Wa  = (const float*)d_in[10];
    const float* ba  = (const float*)d_in[11];
    float* out = (float*)d_out;

    // one-time side-stream + events (host-side handles; no device allocation)
    static cudaStream_t s2 = nullptr;
    static cudaEvent_t evFork = nullptr, evJoin = nullptr;
    if (s2 == nullptr) {
        cudaStreamCreateWithFlags(&s2, cudaStreamNonBlocking);
        cudaEventCreateWithFlags(&evFork, cudaEventDisableTiming);
        cudaEventCreateWithFlags(&evJoin, cudaEventDisableTiming);
    }

    // fork: bias_pre (DRAM-bound, independent) runs parallel to the QKV chain
    cudaEventRecord(evFork, 0);
    cudaStreamWaitEvent(s2, evFork, 0);
    bias_pre<<<Bn * Nn, 256, 0, s2>>>(adj, Wa, ba);
    cudaEventRecord(evJoin, s2);

    // main chain (tensor/issue-bound)
    convert_x<<<(Bn * Nn * En / 4) / 256, 256>>>(x);
    convert_wt<<<4 * 64, 256>>>(Wq, Wk, Wv, Wo);

    dim3 gq(En / 64, (Bn * Nn) / 128, 3);
    gemm_tc<0><<<gq, 256>>>(bq, bk, bv, nullptr, nullptr);

    transpose_v<<<Bn * Hn * (Nn / 32), 256>>>();

    // join: attention needs g_bias
    cudaStreamWaitEvent(0, evJoin, 0);

    dim3 ga(Nn / 128, Hn, Bn);
    attn_tc<<<ga, 256>>>();

    dim3 go(En / 64, (Bn * Nn) / 128);
    gemm_tc<1><<<go, 256>>>(bo, bo, bo, x, out);
}

// round 10
// speedup vs baseline: 2.6892x; 1.1231x over previous
#include <cuda_runtime.h>
#include <cuda_bf16.h>
#include <cuda_fp16.h>
#include <cstdint>

#define Bn 8
#define Nn 1024
#define En 256
#define Hn 8
#define Dn 32
#define Cn 4

#define QSZ (Bn * Hn * Nn * Dn)            // 2M elems
__device__ float d_V[QSZ];
__device__ __half g_xh[Bn * Nn * En];
__device__ __half g_qh[QSZ];
__device__ __half g_kh[QSZ];
__device__ __half g_vth[QSZ];              // [B,H,D,N]
__device__ __half g_ch[Bn * Nn * En];      // ctx row-major
__device__ __half g_wth[4 * En * En];      // W^T: q,k,v,o
__device__ __half g_bias[(size_t)Bn * Hn * Nn * Nn]; // 134MB, log2e-scaled

#define SCALEQ 0.25506807163967554f   // 1/sqrt(32) * log2e
#define LOG2E  1.4426950408889634f

__device__ __forceinline__ float ex2(float x) {
    float y;
    asm("ex2.approx.f32 %0, %1;" : "=f"(y) : "f"(x));
    return y;
}
__device__ __forceinline__ uint32_t bitsh2(__half2 v) {
    return *reinterpret_cast<uint32_t*>(&v);
}
__device__ __forceinline__ uint2 pack4h(float a, float b, float c, float d) {
    uint2 r;
    r.x = bitsh2(__floats2half2_rn(a, b));
    r.y = bitsh2(__floats2half2_rn(c, d));
    return r;
}
__device__ __forceinline__ uint32_t smem_u32(const void* p) {
    uint32_t a;
    asm("{ .reg .u64 t; cvta.to.shared.u64 t, %1; cvt.u32.u64 %0, t; }" : "=r"(a) : "l"(p));
    return a;
}

#define CP_A16(d, s) asm volatile("cp.async.cg.shared.global [%0], [%1], 16;" :: "r"(d), "l"(s) : "memory")
#define CP_COMMIT()  asm volatile("cp.async.commit_group;" ::: "memory")
#define CP_WAIT0()   asm volatile("cp.async.wait_group 0;" ::: "memory")
#define CP_WAIT1()   asm volatile("cp.async.wait_group 1;" ::: "memory")

#define MMAH(c, a, b0, b1)                                                    \
    asm volatile("mma.sync.aligned.m16n8k16.row.col.f32.f16.f16.f32 "         \
        "{%0,%1,%2,%3}, {%4,%5,%6,%7}, {%8,%9}, {%0,%1,%2,%3};"               \
        : "+f"((c)[0]), "+f"((c)[1]), "+f"((c)[2]), "+f"((c)[3])              \
        : "r"((a)[0]), "r"((a)[1]), "r"((a)[2]), "r"((a)[3]), "r"(b0), "r"(b1))

// ============================================================================
// convert x -> fp16
// ============================================================================
__global__ __launch_bounds__(256)
void convert_x(const float* __restrict__ x)
{
    int i = blockIdx.x * 256 + threadIdx.x;   // per float4
    float4 v = ((const float4*)x)[i];
    ((uint2*)g_xh)[i] = pack4h(v.x, v.y, v.z, v.w);
}

// ============================================================================
// convert W -> W^T fp16 (32x32 tiles)
// ============================================================================
__global__ __launch_bounds__(256)
void convert_wt(const float* __restrict__ W0, const float* __restrict__ W1,
                const float* __restrict__ W2, const float* __restrict__ W3)
{
    __shared__ float T[32][33];
    const int z = blockIdx.x >> 6;
    const int tile = blockIdx.x & 63;
    const int k0 = (tile >> 3) * 32;
    const int n0 = (tile & 7) * 32;
    const float* W = (z == 0) ? W0 : (z == 1) ? W1 : (z == 2) ? W2 : W3;
    const int tid = threadIdx.x;
    {
        int r = tid >> 3, c4 = tid & 7;
        float4 v = *(const float4*)&W[(k0 + r) * En + n0 + c4 * 4];
        T[r][c4 * 4 + 0] = v.x; T[r][c4 * 4 + 1] = v.y;
        T[r][c4 * 4 + 2] = v.z; T[r][c4 * 4 + 3] = v.w;
    }
    __syncthreads();
    {
        int r = tid >> 3, c4 = tid & 7;
        int off = z * En * En + (n0 + r) * En + k0 + c4 * 4;
        *(uint2*)&g_wth[off] = pack4h(T[c4 * 4 + 0][r], T[c4 * 4 + 1][r],
                                      T[c4 * 4 + 2][r], T[c4 * 4 + 3][r]);
    }
}

// ============================================================================
// fp16 tensor-core GEMM, cp.async double-buffered.
// C[128x64] tile of A[8192x256] @ B^T.
// MODE 0: QKV (z=blockIdx.z; epilogue -> fp16 Q(scaled)/K, fp32 V)
// MODE 1: out-proj (A=g_ch, W slot 3; epilogue -> +bo +x -> out fp32)
// ============================================================================
#define GBUF_W 3840          // per buffer: A@0 (2560) + B@2560 (1280)
#define GB_OFF 2560

template <int MODE>
__global__ __launch_bounds__(256)
void gemm_tc(const float* __restrict__ bias0, const float* __restrict__ bias1,
             const float* __restrict__ bias2,
             const float* __restrict__ X, float* __restrict__ OutR)
{
    __shared__ __align__(16) uint32_t S[2 * GBUF_W];   // 30 KB
    const uint32_t sb = smem_u32(S);
    const int tid = threadIdx.x;
    const int w = tid >> 5, lane = tid & 31;
    const int g = lane >> 2, t = lane & 3;
    const int row0 = blockIdx.y * 128;
    const int col0 = blockIdx.x * 64;
    const int z = (MODE == 0) ? blockIdx.z : 3;

    const uint4* a4p = (const uint4*)((MODE == 0) ? g_xh : g_ch);
    const uint4* b4p = (const uint4*)(g_wth + z * En * En);

    float c_[8][4] = {};

    const int a_row = tid >> 1;          // 0..127
    const int a_c4 = (tid & 1) * 2;      // uint4 col 0/2
    const int b_row = tid >> 2;          // 0..63
    const int b_c4 = tid & 3;

    auto stage = [&](int kc, int bb) {
        size_t siA = (size_t)(row0 + a_row) * 32 + kc * 4 + a_c4;
        CP_A16(sb + (bb + a_row * 20 + a_c4 * 4) * 4, a4p + siA);
        CP_A16(sb + (bb + a_row * 20 + (a_c4 + 1) * 4) * 4, a4p + siA + 1);
        size_t siB = (size_t)(col0 + b_row) * 32 + kc * 4 + b_c4;
        CP_A16(sb + (bb + GB_OFF + b_row * 20 + b_c4 * 4) * 4, b4p + siB);
        CP_COMMIT();
    };

    stage(0, 0);
    for (int kc = 0; kc < 8; kc++) {
        const int bb = (kc & 1) * GBUF_W;
        if (kc + 1 < 8) {
            stage(kc + 1, ((kc + 1) & 1) * GBUF_W);
            CP_WAIT1();
        } else {
            CP_WAIT0();
        }
        __syncthreads();
#pragma unroll
        for (int kt = 0; kt < 2; kt++) {
            const int aw = bb + (w * 16 + g) * 20 + kt * 8 + t;
            uint32_t a[4];
            a[0] = S[aw];       a[1] = S[aw + 160];
            a[2] = S[aw + 4];   a[3] = S[aw + 164];
#pragma unroll
            for (int nt = 0; nt < 8; nt++) {
                const int kw = bb + GB_OFF + (nt * 8 + g) * 20 + kt * 8 + t;
                MMAH(c_[nt], a, S[kw], S[kw + 4]);
            }
        }
        __syncthreads();
    }

    const int m = row0 + w * 16 + g;
    if (MODE == 0) {
        const float* bias = (z == 0) ? bias0 : (z == 1) ? bias1 : bias2;
        const int b = m >> 10, n = m & 1023;
#pragma unroll
        for (int nt = 0; nt < 8; nt++) {
            int col = col0 + nt * 8 + 2 * t;
            float bz0 = bias[col], bz1 = bias[col + 1];
            float v0 = c_[nt][0] + bz0, v1 = c_[nt][1] + bz1;
            float v2 = c_[nt][2] + bz0, v3 = c_[nt][3] + bz1;
            int h = col >> 5, dd = col & 31;
            size_t oA = ((size_t)(b * Hn + h) * Nn + n) * Dn + dd;
            size_t oB = oA + 8 * Dn;
            if (z == 0) {
                v0 *= SCALEQ; v1 *= SCALEQ; v2 *= SCALEQ; v3 *= SCALEQ;
                *(uint32_t*)&g_qh[oA] = bitsh2(__floats2half2_rn(v0, v1));
                *(uint32_t*)&g_qh[oB] = bitsh2(__floats2half2_rn(v2, v3));
            } else if (z == 1) {
                *(uint32_t*)&g_kh[oA] = bitsh2(__floats2half2_rn(v0, v1));
                *(uint32_t*)&g_kh[oB] = bitsh2(__floats2half2_rn(v2, v3));
            } else {
                float2 p0 = {v0, v1}, p1 = {v2, v3};
                *(float2*)&d_V[oA] = p0;
                *(float2*)&d_V[oB] = p1;
            }
        }
    } else {
#pragma unroll
        for (int nt = 0; nt < 8; nt++) {
            int col = col0 + nt * 8 + 2 * t;
            float bz0 = bias0[col], bz1 = bias0[col + 1];
            float2 xA = *(const float2*)&X[(size_t)m * En + col];
            float2 xB = *(const float2*)&X[(size_t)(m + 8) * En + col];
            float2 oA = {c_[nt][0] + bz0 + xA.x, c_[nt][1] + bz1 + xA.y};
            float2 oB = {c_[nt][2] + bz0 + xB.x, c_[nt][3] + bz1 + xB.y};
            *(float2*)&OutR[(size_t)m * En + col] = oA;
            *(float2*)&OutR[(size_t)(m + 8) * En + col] = oB;
        }
    }
}

// ============================================================================
// transpose V to [B,H,D,N] fp16
// ============================================================================
__global__ __launch_bounds__(256)
void transpose_v()
{
    __shared__ float T[32][36];
    const int tid = threadIdx.x;
    const int blk = blockIdx.x;
    const int bh = blk >> 5, jt = blk & 31;
    const int j0 = jt * 32;
    {
        int r = tid >> 3, c = tid & 7;
        float4 v = *(const float4*)&d_V[(bh * Nn + j0 + r) * Dn + c * 4];
        *(float4*)&T[r][c * 4] = v;
    }
    __syncthreads();
    {
        int d = tid >> 3, c = tid & 7;
        int off = (bh * Dn + d) * Nn + j0 + c * 4;
        *(uint2*)&g_vth[off] = pack4h(T[c * 4 + 0][d], T[c * 4 + 1][d],
                                      T[c * 4 + 2][d], T[c * 4 + 3][d]);
    }
}

// ============================================================================
// bias precompute  bias[b,h,i,j] = (adj[b,i,j,:]@Wa[:,h] + ba[h])*log2e  (fp16)
// ============================================================================
__global__ __launch_bounds__(256)
void bias_pre(const float* __restrict__ adj, const float* __restrict__ Wa,
              const float* __restrict__ ba)
{
    const int tid = threadIdx.x;
    const int b = blockIdx.x >> 10;
    const int i = blockIdx.x & 1023;
    float w2[Cn][Hn], off[Hn];
#pragma unroll
    for (int h = 0; h < Hn; h++) {
        off[h] = ba[h] * LOG2E;
#pragma unroll
        for (int c = 0; c < Cn; c++) w2[c][h] = Wa[c * Hn + h] * LOG2E;
    }
    const float4* a4 = (const float4*)&adj[(size_t)(b * Nn + i) * Nn * Cn];
#pragma unroll
    for (int r = 0; r < 2; r++) {
        int j = (tid + r * 256) * 2;
        float4 x0 = a4[j];
        float4 x1 = a4[j + 1];
#pragma unroll
        for (int h = 0; h < Hn; h++) {
            float v0 = off[h] + x0.x * w2[0][h] + x0.y * w2[1][h] + x0.z * w2[2][h] + x0.w * w2[3][h];
            float v1 = off[h] + x1.x * w2[0][h] + x1.y * w2[1][h] + x1.z * w2[2][h] + x1.w * w2[3][h];
            __half2 hv = __floats2half2_rn(v0, v1);
            *(__half2*)&g_bias[((size_t)(b * Hn + h) * Nn + i) * Nn + j] = hv;
        }
    }
}

// ============================================================================
// fp16 tensor-core flash attention, cp.async double-buffered staging.
// Per buffer (u32 words): K@0 (1280), V^T@1280 (1152), bias@2432 (4608) = 7040.
// 2 buffers = 56,320 bytes dynamic smem.
// ============================================================================
#define ABUF_W 7040
#define K_W 0
#define V_W 1280
#define BIAS_W 2432
#define ATTN_SMEM_BYTES (2 * ABUF_W * 4)

__global__ __launch_bounds__(256)
void attn_tc()
{
    extern __shared__ __align__(16) uint32_t S[];
    const uint32_t sb = smem_u32(S);
    const int tid = threadIdx.x;
    const int w = tid >> 5, lane = tid & 31;
    const int g = lane >> 2, t = lane & 3;
    const int i0 = blockIdx.x * 128;
    const int bh = blockIdx.z * Hn + blockIdx.y;

    const uint32_t* q32 = (const uint32_t*)g_qh;
    const int rowA = bh * Nn + i0 + w * 16 + g;
    const int rowB = rowA + 8;
    uint32_t aQ[2][4];
#pragma unroll
    for (int kt = 0; kt < 2; kt++) {
        aQ[kt][0] = q32[rowA * 16 + kt * 8 + t];
        aQ[kt][1] = q32[rowB * 16 + kt * 8 + t];
        aQ[kt][2] = q32[rowA * 16 + kt * 8 + 4 + t];
        aQ[kt][3] = q32[rowB * 16 + kt * 8 + 4 + t];
    }

    float O[4][4] = {};
    float lA = 0.f, lB = 0.f;

    const uint4* k4p = (const uint4*)g_kh;
    const uint4* v4p = (const uint4*)g_vth;
    const uint4* bg4 = (const uint4*)g_bias;

    const int k_row = tid >> 2, k_c = tid & 3;
    const int v_d = tid >> 3, v_c = tid & 7;

    auto stage = [&](int jt, int bb) {
        const int j0 = jt * 64;
        CP_A16(sb + (bb + K_W + k_row * 20 + k_c * 4) * 4,
               k4p + (bh * Nn + j0 + k_row) * 4 + k_c);
        CP_A16(sb + (bb + V_W + v_d * 36 + v_c * 4) * 4,
               v4p + (bh * Dn + v_d) * 128 + jt * 8 + v_c);
#pragma unroll
        for (int r = 0; r < 4; r++) {
            int idx = tid + r * 256;
            int row = idx >> 3, c = idx & 7;
            CP_A16(sb + (bb + BIAS_W + row * 36 + c * 4) * 4,
                   bg4 + ((size_t)(bh * Nn) + i0 + row) * 128 + jt * 8 + c);
        }
        CP_COMMIT();
    };

    stage(0, 0);
    for (int jt = 0; jt < 16; jt++) {
        const int bb = (jt & 1) * ABUF_W;
        if (jt + 1 < 16) {
            stage(jt + 1, ((jt + 1) & 1) * ABUF_W);
            CP_WAIT1();
        } else {
            CP_WAIT0();
        }
        __syncthreads();

        // ---- QK^T ----
        float c_[8][4] = {};
#pragma unroll
        for (int nt = 0; nt < 8; nt++) {
#pragma unroll
            for (int kt = 0; kt < 2; kt++) {
                int kw = bb + K_W + (nt * 8 + g) * 20 + kt * 8 + t;
                MMAH(c_[nt], aQ[kt], S[kw], S[kw + 4]);
            }
        }
        // ---- + bias from smem ----
        const int biA = bb + BIAS_W + (w * 16 + g) * 36;
        const int biB = biA + 8 * 36;
#pragma unroll
        for (int nt = 0; nt < 8; nt++) {
            uint32_t u0 = S[biA + nt * 4 + t];
            uint32_t u1 = S[biB + nt * 4 + t];
            __half2 h0 = *(__half2*)&u0;
            __half2 h1 = *(__half2*)&u1;
            c_[nt][0] += __low2float(h0);
            c_[nt][1] += __high2float(h0);
            c_[nt][2] += __low2float(h1);
            c_[nt][3] += __high2float(h1);
        }
        // ---- P = exp2(s) ----
        uint32_t PH[8], PH2[8];
#pragma unroll
        for (int nt = 0; nt < 8; nt++) {
            float p0 = ex2(c_[nt][0]), p1 = ex2(c_[nt][1]);
            float p2 = ex2(c_[nt][2]), p3 = ex2(c_[nt][3]);
            lA += p0 + p1;
            lB += p2 + p3;
            PH[nt]  = bitsh2(__floats2half2_rn(p0, p1));
            PH2[nt] = bitsh2(__floats2half2_rn(p2, p3));
        }
        // ---- PV ----
#pragma unroll
        for (int dnt = 0; dnt < 4; dnt++) {
#pragma unroll
            for (int u = 0; u < 4; u++) {
                int vw = bb + V_W + (dnt * 8 + g) * 36 + u * 8 + t;
                uint32_t aP[4] = {PH[2 * u], PH2[2 * u], PH[2 * u + 1], PH2[2 * u + 1]};
                MMAH(O[dnt], aP, S[vw], S[vw + 4]);
            }
        }
        __syncthreads();
    }

    lA += __shfl_xor_sync(0xffffffffu, lA, 1);
    lA += __shfl_xor_sync(0xffffffffu, lA, 2);
    lB += __shfl_xor_sync(0xffffffffu, lB, 1);
    lB += __shfl_xor_sync(0xffffffffu, lB, 2);
    const float iA = 1.f / lA, iB = 1.f / lB;

    const int b = bh >> 3, h = bh & 7;
    const int nA = rowA & (Nn - 1);
    const size_t baseA = ((size_t)b * Nn + nA) * En + h * Dn;
    const size_t baseB = baseA + 8 * En;
#pragma unroll
    for (int dnt = 0; dnt < 4; dnt++) {
        int dd = dnt * 8 + 2 * t;
        *(uint32_t*)&g_ch[baseA + dd] = bitsh2(__floats2half2_rn(O[dnt][0] * iA, O[dnt][1] * iA));
        *(uint32_t*)&g_ch[baseB + dd] = bitsh2(__floats2half2_rn(O[dnt][2] * iB, O[dnt][3] * iB));
    }
}

// ============================================================================
extern "C" void kernel_launch(void* const* d_in, const int* in_sizes, int n_in,
                              void* d_out, int out_size)
{
    const float* x   = (const float*)d_in[0];
    const float* adj = (const float*)d_in[1];
    const float* Wq  = (const float*)d_in[2];
    const float* bq  = (const float*)d_in[3];
    const float* Wk  = (const float*)d_in[4];
    const float* bk  = (const float*)d_in[5];
    const float* Wv  = (const float*)d_in[6];
    const float* bv  = (const float*)d_in[7];
    const float* Wo  = (const float*)d_in[8];
    const float* bo  = (const float*)d_in[9];
    const float* Wa  = (const float*)d_in[10];
    const float* ba  = (const float*)d_in[11];
    float* out = (float*)d_out;

    // one-time side-stream + events + smem attribute (host-side; no device alloc)
    static cudaStream_t s2 = nullptr;
    static cudaEvent_t evFork = nullptr, evJoin = nullptr;
    if (s2 == nullptr) {
        cudaStreamCreateWithFlags(&s2, cudaStreamNonBlocking);
        cudaEventCreateWithFlags(&evFork, cudaEventDisableTiming);
        cudaEventCreateWithFlags(&evJoin, cudaEventDisableTiming);
        cudaFuncSetAttribute(attn_tc, cudaFuncAttributeMaxDynamicSharedMemorySize,
                             ATTN_SMEM_BYTES);
    }

    // fork: bias_pre (DRAM-bound, independent) alongside the QKV chain
    cudaEventRecord(evFork, 0);
    cudaStreamWaitEvent(s2, evFork, 0);
    bias_pre<<<Bn * Nn, 256, 0, s2>>>(adj, Wa, ba);
    cudaEventRecord(evJoin, s2);

    // main chain
    convert_x<<<(Bn * Nn * En / 4) / 256, 256>>>(x);
    convert_wt<<<4 * 64, 256>>>(Wq, Wk, Wv, Wo);

    dim3 gq(En / 64, (Bn * Nn) / 128, 3);
    gemm_tc<0><<<gq, 256>>>(bq, bk, bv, nullptr, nullptr);

    transpose_v<<<Bn * Hn * (Nn / 32), 256>>>();

    // join: attention needs g_bias
    cudaStreamWaitEvent(0, evJoin, 0);

    dim3 ga(Nn / 128, Hn, Bn);
    attn_tc<<<ga, 256, ATTN_SMEM_BYTES>>>();

    dim3 go(En / 64, (Bn * Nn) / 128);
    gemm_tc<1><<<go, 256>>>(bo, bo, bo, x, out);
}

// round 11
// speedup vs baseline: 2.7246x; 1.0132x over previous
#include <cuda_runtime.h>
#include <cuda_bf16.h>
#include <cuda_fp16.h>
#include <cstdint>

#define Bn 8
#define Nn 1024
#define En 256
#define Hn 8
#define Dn 32
#define Cn 4

#define QSZ (Bn * Hn * Nn * Dn)            // 2M elems
__device__ __half g_xh[Bn * Nn * En];
__device__ __half g_qh[QSZ];
__device__ __half g_kh[QSZ];
__device__ __half g_vth[QSZ];              // [B,H,D,N]
__device__ __half g_ch[Bn * Nn * En];      // ctx row-major
__device__ __half g_wth[4 * En * En];      // W^T: q,k,v,o
__device__ __half g_bias[(size_t)Bn * Hn * Nn * Nn]; // 134MB, log2e-scaled

#define SCALEQ 0.25506807163967554f   // 1/sqrt(32) * log2e
#define LOG2E  1.4426950408889634f

__device__ __forceinline__ float ex2(float x) {
    float y;
    asm("ex2.approx.f32 %0, %1;" : "=f"(y) : "f"(x));
    return y;
}
__device__ __forceinline__ uint32_t bitsh2(__half2 v) {
    return *reinterpret_cast<uint32_t*>(&v);
}
__device__ __forceinline__ uint2 pack4h(float a, float b, float c, float d) {
    uint2 r;
    r.x = bitsh2(__floats2half2_rn(a, b));
    r.y = bitsh2(__floats2half2_rn(c, d));
    return r;
}
__device__ __forceinline__ uint32_t smem_u32(const void* p) {
    uint32_t a;
    asm("{ .reg .u64 t; cvta.to.shared.u64 t, %1; cvt.u32.u64 %0, t; }" : "=r"(a) : "l"(p));
    return a;
}

#define CP_A16(d, s) asm volatile("cp.async.cg.shared.global [%0], [%1], 16;" :: "r"(d), "l"(s) : "memory")
#define CP_COMMIT()  asm volatile("cp.async.commit_group;" ::: "memory")
#define CP_WAIT0()   asm volatile("cp.async.wait_group 0;" ::: "memory")
#define CP_WAIT1()   asm volatile("cp.async.wait_group 1;" ::: "memory")

#define MMAH(c, a, b0, b1)                                                    \
    asm volatile("mma.sync.aligned.m16n8k16.row.col.f32.f16.f16.f32 "         \
        "{%0,%1,%2,%3}, {%4,%5,%6,%7}, {%8,%9}, {%0,%1,%2,%3};"               \
        : "+f"((c)[0]), "+f"((c)[1]), "+f"((c)[2]), "+f"((c)[3])              \
        : "r"((a)[0]), "r"((a)[1]), "r"((a)[2]), "r"((a)[3]), "r"(b0), "r"(b1))

// ============================================================================
// convert x -> fp16
// ============================================================================
__global__ __launch_bounds__(256)
void convert_x(const float* __restrict__ x)
{
    int i = blockIdx.x * 256 + threadIdx.x;   // per float4
    float4 v = ((const float4*)x)[i];
    ((uint2*)g_xh)[i] = pack4h(v.x, v.y, v.z, v.w);
}

// ============================================================================
// convert W -> W^T fp16 (32x32 tiles)
// ============================================================================
__global__ __launch_bounds__(256)
void convert_wt(const float* __restrict__ W0, const float* __restrict__ W1,
                const float* __restrict__ W2, const float* __restrict__ W3)
{
    __shared__ float T[32][33];
    const int z = blockIdx.x >> 6;
    const int tile = blockIdx.x & 63;
    const int k0 = (tile >> 3) * 32;
    const int n0 = (tile & 7) * 32;
    const float* W = (z == 0) ? W0 : (z == 1) ? W1 : (z == 2) ? W2 : W3;
    const int tid = threadIdx.x;
    {
        int r = tid >> 3, c4 = tid & 7;
        float4 v = *(const float4*)&W[(k0 + r) * En + n0 + c4 * 4];
        T[r][c4 * 4 + 0] = v.x; T[r][c4 * 4 + 1] = v.y;
        T[r][c4 * 4 + 2] = v.z; T[r][c4 * 4 + 3] = v.w;
    }
    __syncthreads();
    {
        int r = tid >> 3, c4 = tid & 7;
        int off = z * En * En + (n0 + r) * En + k0 + c4 * 4;
        *(uint2*)&g_wth[off] = pack4h(T[c4 * 4 + 0][r], T[c4 * 4 + 1][r],
                                      T[c4 * 4 + 2][r], T[c4 * 4 + 3][r]);
    }
}

// ============================================================================
// fp16 tensor-core GEMM, cp.async double-buffered.
// C[128x64] tile of A[8192x256] @ B^T.
// MODE 0: QKV (z=blockIdx.z; epilogue -> fp16 Q(scaled)/K; V transposed+fp16
//          through smem restage -> g_vth [B,H,D,N], no separate kernel)
// MODE 1: out-proj (A=g_ch, W slot 3; epilogue -> +bo +x -> out fp32)
// ============================================================================
#define GBUF_W 3840          // per buffer: A@0 (2560) + B@2560 (1280)
#define GB_OFF 2560

template <int MODE>
__global__ __launch_bounds__(256)
void gemm_tc(const float* __restrict__ bias0, const float* __restrict__ bias1,
             const float* __restrict__ bias2,
             const float* __restrict__ X, float* __restrict__ OutR)
{
    __shared__ __align__(16) uint32_t S[2 * GBUF_W];   // 30 KB
    const uint32_t sb = smem_u32(S);
    const int tid = threadIdx.x;
    const int w = tid >> 5, lane = tid & 31;
    const int g = lane >> 2, t = lane & 3;
    const int row0 = blockIdx.y * 128;
    const int col0 = blockIdx.x * 64;
    const int z = (MODE == 0) ? blockIdx.z : 3;

    const uint4* a4p = (const uint4*)((MODE == 0) ? g_xh : g_ch);
    const uint4* b4p = (const uint4*)(g_wth + z * En * En);

    float c_[8][4] = {};

    const int a_row = tid >> 1;          // 0..127
    const int a_c4 = (tid & 1) * 2;      // uint4 col 0/2
    const int b_row = tid >> 2;          // 0..63
    const int b_c4 = tid & 3;

    auto stage = [&](int kc, int bb) {
        size_t siA = (size_t)(row0 + a_row) * 32 + kc * 4 + a_c4;
        CP_A16(sb + (bb + a_row * 20 + a_c4 * 4) * 4, a4p + siA);
        CP_A16(sb + (bb + a_row * 20 + (a_c4 + 1) * 4) * 4, a4p + siA + 1);
        size_t siB = (size_t)(col0 + b_row) * 32 + kc * 4 + b_c4;
        CP_A16(sb + (bb + GB_OFF + b_row * 20 + b_c4 * 4) * 4, b4p + siB);
        CP_COMMIT();
    };

    stage(0, 0);
    for (int kc = 0; kc < 8; kc++) {
        const int bb = (kc & 1) * GBUF_W;
        if (kc + 1 < 8) {
            stage(kc + 1, ((kc + 1) & 1) * GBUF_W);
            CP_WAIT1();
        } else {
            CP_WAIT0();
        }
        __syncthreads();
#pragma unroll
        for (int kt = 0; kt < 2; kt++) {
            const int aw = bb + (w * 16 + g) * 20 + kt * 8 + t;
            uint32_t a[4];
            a[0] = S[aw];       a[1] = S[aw + 160];
            a[2] = S[aw + 4];   a[3] = S[aw + 164];
#pragma unroll
            for (int nt = 0; nt < 8; nt++) {
                const int kw = bb + GB_OFF + (nt * 8 + g) * 20 + kt * 8 + t;
                MMAH(c_[nt], a, S[kw], S[kw + 4]);
            }
        }
        __syncthreads();
    }

    const int m = row0 + w * 16 + g;
    if (MODE == 0) {
        const float* bias = (z == 0) ? bias0 : (z == 1) ? bias1 : bias2;
        const int b = row0 >> 10, n0 = row0 & 1023;
        const int n = m & 1023;
        if (z < 2) {
#pragma unroll
            for (int nt = 0; nt < 8; nt++) {
                int col = col0 + nt * 8 + 2 * t;
                float bz0 = bias[col], bz1 = bias[col + 1];
                float v0 = c_[nt][0] + bz0, v1 = c_[nt][1] + bz1;
                float v2 = c_[nt][2] + bz0, v3 = c_[nt][3] + bz1;
                int h = col >> 5, dd = col & 31;
                size_t oA = ((size_t)(b * Hn + h) * Nn + n) * Dn + dd;
                size_t oB = oA + 8 * Dn;
                if (z == 0) {
                    v0 *= SCALEQ; v1 *= SCALEQ; v2 *= SCALEQ; v3 *= SCALEQ;
                    *(uint32_t*)&g_qh[oA] = bitsh2(__floats2half2_rn(v0, v1));
                    *(uint32_t*)&g_qh[oB] = bitsh2(__floats2half2_rn(v2, v3));
                } else {
                    *(uint32_t*)&g_kh[oA] = bitsh2(__floats2half2_rn(v0, v1));
                    *(uint32_t*)&g_kh[oB] = bitsh2(__floats2half2_rn(v2, v3));
                }
            }
        } else {
            // V: transpose through smem (k-loop done; S reusable) -> g_vth [B,H,D,N]
            __half* S2 = (__half*)S;       // 64 cols x 136-pitch rows of 128 = 17.4 KB
            const int lr = w * 16 + g;
#pragma unroll
            for (int nt = 0; nt < 8; nt++) {
                int lc = nt * 8 + 2 * t;
                int col = col0 + lc;
                float bz0 = bias[col], bz1 = bias[col + 1];
                S2[lc * 136 + lr]           = __float2half_rn(c_[nt][0] + bz0);
                S2[(lc + 1) * 136 + lr]     = __float2half_rn(c_[nt][1] + bz1);
                S2[lc * 136 + lr + 8]       = __float2half_rn(c_[nt][2] + bz0);
                S2[(lc + 1) * 136 + lr + 8] = __float2half_rn(c_[nt][3] + bz1);
            }
            __syncthreads();
            const int colx = tid >> 2, seg = tid & 3;
            const int gc = col0 + colx;
            const int h = gc >> 5, dd = gc & 31;
            size_t dst = ((size_t)(b * Hn + h) * Dn + dd) * Nn + n0 + seg * 32;
            const uint4* sp = (const uint4*)&S2[colx * 136 + seg * 32];
            uint4* dp = (uint4*)&g_vth[dst];
            dp[0] = sp[0]; dp[1] = sp[1]; dp[2] = sp[2]; dp[3] = sp[3];
        }
    } else {
#pragma unroll
        for (int nt = 0; nt < 8; nt++) {
            int col = col0 + nt * 8 + 2 * t;
            float bz0 = bias0[col], bz1 = bias0[col + 1];
            float2 xA = *(const float2*)&X[(size_t)m * En + col];
            float2 xB = *(const float2*)&X[(size_t)(m + 8) * En + col];
            float2 oA = {c_[nt][0] + bz0 + xA.x, c_[nt][1] + bz1 + xA.y};
            float2 oB = {c_[nt][2] + bz0 + xB.x, c_[nt][3] + bz1 + xB.y};
            *(float2*)&OutR[(size_t)m * En + col] = oA;
            *(float2*)&OutR[(size_t)(m + 8) * En + col] = oB;
        }
    }
}

// ============================================================================
// bias precompute  bias[b,h,i,j] = (adj[b,i,j,:]@Wa[:,h] + ba[h])*log2e  (fp16)
// Half-batch per launch (b0). Wa/ba in smem; streaming loads/stores.
// ============================================================================
__global__ __launch_bounds__(256)
void bias_pre(const float* __restrict__ adj, const float* __restrict__ Wa,
              const float* __restrict__ ba, int b0)
{
    __shared__ float ws[Cn * Hn];
    __shared__ float offs[Hn];
    const int tid = threadIdx.x;
    if (tid < Cn * Hn) ws[tid] = Wa[tid] * LOG2E;   // ws[c*Hn+h]
    if (tid < Hn) offs[tid] = ba[tid] * LOG2E;
    __syncthreads();

    const int b = b0 + (blockIdx.x >> 10);
    const int i = blockIdx.x & 1023;
    const float4* a4 = (const float4*)&adj[(size_t)(b * Nn + i) * Nn * Cn];
#pragma unroll
    for (int r = 0; r < 2; r++) {
        int j = (tid + r * 256) * 2;
        float4 x0 = __ldcs(a4 + j);
        float4 x1 = __ldcs(a4 + j + 1);
#pragma unroll 1
        for (int h = 0; h < Hn; h++) {
            float w0 = ws[h], w1 = ws[8 + h], w2 = ws[16 + h], w3 = ws[24 + h];
            float o = offs[h];
            float v0 = o + x0.x * w0 + x0.y * w1 + x0.z * w2 + x0.w * w3;
            float v1 = o + x1.x * w0 + x1.y * w1 + x1.z * w2 + x1.w * w3;
            __stcs((__half2*)&g_bias[((size_t)((b * Hn + h) * Nn + i)) * Nn + j],
                   __floats2half2_rn(v0, v1));
        }
    }
}

// ============================================================================
// fp16 tensor-core flash attention, cp.async double-buffered staging.
// Half-batch per launch (b0) so it overlaps the other half's bias_pre.
// Per buffer (u32 words): K@0 (1280), V^T@1280 (1152), bias@2432 (4608) = 7040.
// ============================================================================
#define ABUF_W 7040
#define K_W 0
#define V_W 1280
#define BIAS_W 2432
#define ATTN_SMEM_BYTES (2 * ABUF_W * 4)

__global__ __launch_bounds__(256)
void attn_tc(int b0)
{
    extern __shared__ __align__(16) uint32_t S[];
    const uint32_t sb = smem_u32(S);
    const int tid = threadIdx.x;
    const int w = tid >> 5, lane = tid & 31;
    const int g = lane >> 2, t = lane & 3;
    const int i0 = blockIdx.x * 128;
    const int bh = (b0 + blockIdx.z) * Hn + blockIdx.y;

    const uint32_t* q32 = (const uint32_t*)g_qh;
    const int rowA = bh * Nn + i0 + w * 16 + g;
    const int rowB = rowA + 8;
    uint32_t aQ[2][4];
#pragma unroll
    for (int kt = 0; kt < 2; kt++) {
        aQ[kt][0] = q32[rowA * 16 + kt * 8 + t];
        aQ[kt][1] = q32[rowB * 16 + kt * 8 + t];
        aQ[kt][2] = q32[rowA * 16 + kt * 8 + 4 + t];
        aQ[kt][3] = q32[rowB * 16 + kt * 8 + 4 + t];
    }

    float O[4][4] = {};
    float lA = 0.f, lB = 0.f;

    const uint4* k4p = (const uint4*)g_kh;
    const uint4* v4p = (const uint4*)g_vth;
    const uint4* bg4 = (const uint4*)g_bias;

    const int k_row = tid >> 2, k_c = tid & 3;
    const int v_d = tid >> 3, v_c = tid & 7;

    auto stage = [&](int jt, int bb) {
        const int j0 = jt * 64;
        CP_A16(sb + (bb + K_W + k_row * 20 + k_c * 4) * 4,
               k4p + (bh * Nn + j0 + k_row) * 4 + k_c);
        CP_A16(sb + (bb + V_W + v_d * 36 + v_c * 4) * 4,
               v4p + (bh * Dn + v_d) * 128 + jt * 8 + v_c);
#pragma unroll
        for (int r = 0; r < 4; r++) {
            int idx = tid + r * 256;
            int row = idx >> 3, c = idx & 7;
            CP_A16(sb + (bb + BIAS_W + row * 36 + c * 4) * 4,
                   bg4 + ((size_t)(bh * Nn) + i0 + row) * 128 + jt * 8 + c);
        }
        CP_COMMIT();
    };

    stage(0, 0);
    for (int jt = 0; jt < 16; jt++) {
        const int bb = (jt & 1) * ABUF_W;
        if (jt + 1 < 16) {
            stage(jt + 1, ((jt + 1) & 1) * ABUF_W);
            CP_WAIT1();
        } else {
            CP_WAIT0();
        }
        __syncthreads();

        // ---- QK^T ----
        float c_[8][4] = {};
#pragma unroll
        for (int nt = 0; nt < 8; nt++) {
#pragma unroll
            for (int kt = 0; kt < 2; kt++) {
                int kw = bb + K_W + (nt * 8 + g) * 20 + kt * 8 + t;
                MMAH(c_[nt], aQ[kt], S[kw], S[kw + 4]);
            }
        }
        // ---- + bias from smem ----
        const int biA = bb + BIAS_W + (w * 16 + g) * 36;
        const int biB = biA + 8 * 36;
#pragma unroll
        for (int nt = 0; nt < 8; nt++) {
            uint32_t u0 = S[biA + nt * 4 + t];
            uint32_t u1 = S[biB + nt * 4 + t];
            __half2 h0 = *(__half2*)&u0;
            __half2 h1 = *(__half2*)&u1;
            c_[nt][0] += __low2float(h0);
            c_[nt][1] += __high2float(h0);
            c_[nt][2] += __low2float(h1);
            c_[nt][3] += __high2float(h1);
        }
        // ---- P = exp2(s) ----
        uint32_t PH[8], PH2[8];
#pragma unroll
        for (int nt = 0; nt < 8; nt++) {
            float p0 = ex2(c_[nt][0]), p1 = ex2(c_[nt][1]);
            float p2 = ex2(c_[nt][2]), p3 = ex2(c_[nt][3]);
            lA += p0 + p1;
            lB += p2 + p3;
            PH[nt]  = bitsh2(__floats2half2_rn(p0, p1));
            PH2[nt] = bitsh2(__floats2half2_rn(p2, p3));
        }
        // ---- PV ----
#pragma unroll
        for (int dnt = 0; dnt < 4; dnt++) {
#pragma unroll
            for (int u = 0; u < 4; u++) {
                int vw = bb + V_W + (dnt * 8 + g) * 36 + u * 8 + t;
                uint32_t aP[4] = {PH[2 * u], PH2[2 * u], PH[2 * u + 1], PH2[2 * u + 1]};
                MMAH(O[dnt], aP, S[vw], S[vw + 4]);
            }
        }
        __syncthreads();
    }

    lA += __shfl_xor_sync(0xffffffffu, lA, 1);
    lA += __shfl_xor_sync(0xffffffffu, lA, 2);
    lB += __shfl_xor_sync(0xffffffffu, lB, 1);
    lB += __shfl_xor_sync(0xffffffffu, lB, 2);
    const float iA = 1.f / lA, iB = 1.f / lB;

    const int b = bh >> 3, h = bh & 7;
    const int nA = rowA & (Nn - 1);
    const size_t baseA = ((size_t)b * Nn + nA) * En + h * Dn;
    const size_t baseB = baseA + 8 * En;
#pragma unroll
    for (int dnt = 0; dnt < 4; dnt++) {
        int dd = dnt * 8 + 2 * t;
        *(uint32_t*)&g_ch[baseA + dd] = bitsh2(__floats2half2_rn(O[dnt][0] * iA, O[dnt][1] * iA));
        *(uint32_t*)&g_ch[baseB + dd] = bitsh2(__floats2half2_rn(O[dnt][2] * iB, O[dnt][3] * iB));
    }
}

// ============================================================================
extern "C" void kernel_launch(void* const* d_in, const int* in_sizes, int n_in,
                              void* d_out, int out_size)
{
    const float* x   = (const float*)d_in[0];
    const float* adj = (const float*)d_in[1];
    const float* Wq  = (const float*)d_in[2];
    const float* bq  = (const float*)d_in[3];
    const float* Wk  = (const float*)d_in[4];
    const float* bk  = (const float*)d_in[5];
    const float* Wv  = (const float*)d_in[6];
    const float* bv  = (const float*)d_in[7];
    const float* Wo  = (const float*)d_in[8];
    const float* bo  = (const float*)d_in[9];
    const float* Wa  = (const float*)d_in[10];
    const float* ba  = (const float*)d_in[11];
    float* out = (float*)d_out;

    // one-time side-stream + events + smem attribute (host-side; no device alloc)
    static cudaStream_t s2 = nullptr;
    static cudaEvent_t evFork = nullptr, evB1 = nullptr, evB2 = nullptr;
    if (s2 == nullptr) {
        cudaStreamCreateWithFlags(&s2, cudaStreamNonBlocking);
        cudaEventCreateWithFlags(&evFork, cudaEventDisableTiming);
        cudaEventCreateWithFlags(&evB1, cudaEventDisableTiming);
        cudaEventCreateWithFlags(&evB2, cudaEventDisableTiming);
        cudaFuncSetAttribute(attn_tc, cudaFuncAttributeMaxDynamicSharedMemorySize,
                             ATTN_SMEM_BYTES);
    }

    // fork: bias_pre in two batch halves on side stream
    cudaEventRecord(evFork, 0);
    cudaStreamWaitEvent(s2, evFork, 0);
    bias_pre<<<(Bn / 2) * Nn, 256, 0, s2>>>(adj, Wa, ba, 0);
    cudaEventRecord(evB1, s2);
    bias_pre<<<(Bn / 2) * Nn, 256, 0, s2>>>(adj, Wa, ba, 4);
    cudaEventRecord(evB2, s2);

    // main chain: converts + QKV GEMM (V transposed+converted in epilogue)
    convert_x<<<(Bn * Nn * En / 4) / 256, 256>>>(x);
    convert_wt<<<4 * 64, 256>>>(Wq, Wk, Wv, Wo);

    dim3 gq(En / 64, (Bn * Nn) / 128, 3);
    gemm_tc<0><<<gq, 256>>>(bq, bk, bv, nullptr, nullptr);

    // attention half 1 (overlaps bias_pre half 2 on s2)
    cudaStreamWaitEvent(0, evB1, 0);
    dim3 ga(Nn / 128, Hn, Bn / 2);
    attn_tc<<<ga, 256, ATTN_SMEM_BYTES>>>(0);

    // attention half 2
    cudaStreamWaitEvent(0, evB2, 0);
    attn_tc<<<ga, 256, ATTN_SMEM_BYTES>>>(4);

    // output projection + residual
    dim3 go(En / 64, (Bn * Nn) / 128);
    gemm_tc<1><<<go, 256>>>(bo, bo, bo, x, out);
}